// round 6
// baseline (speedup 1.0000x reference)
#include <cuda_runtime.h>

#define F_ 48
#define G_ 4
#define C_ 128
#define GF 192
#define NPIX 64
#define THREADS 384
#define WFS 196            // padded Wf row stride (mult of 4 -> float4 weight loads)
#define SCALE_C 0.999f

// shared memory layout (floats)
#define OFF_WF   0
#define OFF_X    (OFF_WF + C_*WFS)
#define OFF_BUF  (OFF_X + C_*NPIX)
#define OFF_QE   (OFF_BUF + GF*NPIX)
#define OFF_QM   (OFF_QE + F_*16)
#define OFF_ITS  (OFF_QM + F_*16)
#define OFF_ISC  (OFF_ITS + F_)
#define OFF_LSC  (OFF_ISC + F_)
#define SMEM_FLOATS (OFF_LSC + F_)
#define SMEM_BYTES (SMEM_FLOATS * 4)

struct Precomp {
    float Qeff[F_][G_][G_];
    float Qm[F_][G_][G_];
    float its[F_];
    float invsc[2][F_];
    float lscal[2][F_];
    float eps_e;
    float inv_denom;
};
__device__ Precomp g_pre;

// ---------------- packed f32x2 helpers (sm_103a) ----------------
__device__ __forceinline__ unsigned long long pack2(float a, float b) {
    unsigned long long r;
    asm("mov.b64 %0,{%1,%2};" : "=l"(r) : "f"(a), "f"(b));
    return r;
}
__device__ __forceinline__ void fma2(unsigned long long& d,
                                     unsigned long long a,
                                     unsigned long long b) {
    asm("fma.rn.f32x2 %0,%1,%2,%0;" : "+l"(d) : "l"(a), "l"(b));
}
__device__ __forceinline__ float2 unpack2(unsigned long long v) {
    float2 r;
    asm("mov.b64 {%0,%1},%2;" : "=f"(r.x), "=f"(r.y) : "l"(v));
    return r;
}

// ---------------- l1-ball projection for a 4-vector ----------------
__device__ __forceinline__ void proj4(float x0, float x1, float x2, float x3,
                                      float& o0, float& o1, float& o2, float& o3) {
    float a0 = fabsf(x0), a1 = fabsf(x1), a2 = fabsf(x2), a3 = fabsf(x3);
    float ssum = a0 + a1 + a2 + a3;
    float m01 = fmaxf(a0, a1), n01 = fminf(a0, a1);
    float m23 = fmaxf(a2, a3), n23 = fminf(a2, a3);
    float s0 = fmaxf(m01, m23), lo0 = fminf(m01, m23);
    float hi1 = fmaxf(n01, n23), s3 = fminf(n01, n23);
    float s1 = fmaxf(lo0, hi1), s2 = fminf(lo0, hi1);
    float c1 = s0 - 1.f, c2 = c1 + s1, c3 = c2 + s2, c4 = c3 + s3;
    int rho = 1 + (s1 * 2.f > c2) + (s2 * 3.f > c3) + (s3 * 4.f > c4);
    float num = (rho == 1) ? c1 : (rho == 2) ? c2 : (rho == 3) ? c3 : c4;
    float theta = fmaxf(num / (float)rho, 0.f);
    theta = (ssum <= 1.f) ? 0.f : theta;
    o0 = copysignf(fmaxf(a0 - theta, 0.f), x0);
    o1 = copysignf(fmaxf(a1 - theta, 0.f), x1);
    o2 = copysignf(fmaxf(a2 - theta, 0.f), x2);
    o3 = copysignf(fmaxf(a3 - theta, 0.f), x3);
}

// ---------------- precompute kernel ----------------
__global__ void precomp_kernel(const float* __restrict__ sigma,
                               const float* __restrict__ Qp,
                               const float* __restrict__ tausp,
                               const float* __restrict__ lambp,
                               const float* __restrict__ epsp,
                               const float* __restrict__ w1, const float* __restrict__ b1,
                               const float* __restrict__ w2, const float* __restrict__ b2,
                               const float* __restrict__ w3, const float* __restrict__ b3) {
    __shared__ float h1[2][F_], h2[2][F_];
    int t = threadIdx.x;
    float lamb_e = expf(lambp[0]);
    float eps_e = expf(epsp[0]);
    if (t == 0) {
        g_pre.eps_e = eps_e;
        g_pre.inv_denom = 1.f / (1.f + lamb_e * (1.f + eps_e));
    }
    if (t < F_) {
        float Qm[G_][G_];
#pragma unroll
        for (int l = 0; l < 4; l++) {
            float rs = 0.f;
#pragma unroll
            for (int g = 0; g < 4; g++) rs += fabsf(Qp[t * 16 + l * 4 + g]);
            float inv = 1.f / fmaxf(rs, 1.f);
#pragma unroll
            for (int g = 0; g < 4; g++) Qm[l][g] = Qp[t * 16 + l * 4 + g] * inv;
        }
        double S[4][4];
        for (int i = 0; i < 4; i++)
            for (int j = 0; j < 4; j++) {
                double acc = 0.0;
                for (int l = 0; l < 4; l++) acc += (double)Qm[l][i] * (double)Qm[l][j];
                S[i][j] = acc;
            }
        const int JP[6] = {0, 0, 0, 1, 1, 2};
        const int JQ[6] = {1, 2, 3, 2, 3, 3};
        for (int sw = 0; sw < 25; sw++)
            for (int r = 0; r < 6; r++) {
                int p = JP[r], q = JQ[r];
                double apq = S[p][q];
                if (fabs(apq) < 1e-30) continue;
                double th = (S[q][q] - S[p][p]) / (2.0 * apq);
                double tt = (th >= 0.0 ? 1.0 : -1.0) / (fabs(th) + sqrt(1.0 + th * th));
                double cc = 1.0 / sqrt(1.0 + tt * tt), ss = tt * cc;
                for (int k = 0; k < 4; k++) {
                    double skp = S[k][p], skq = S[k][q];
                    S[k][p] = cc * skp - ss * skq;
                    S[k][q] = ss * skp + cc * skq;
                }
                for (int k = 0; k < 4; k++) {
                    double spk = S[p][k], sqk = S[q][k];
                    S[p][k] = cc * spk - ss * sqk;
                    S[q][k] = ss * spk + cc * sqk;
                }
            }
        double lam = S[0][0];
        for (int i = 1; i < 4; i++) lam = (S[i][i] > lam) ? S[i][i] : lam;
        float inv_lam = (float)(1.0 / lam);
#pragma unroll
        for (int l = 0; l < 4; l++)
#pragma unroll
            for (int g = 0; g < 4; g++) {
                g_pre.Qm[t][l][g] = Qm[l][g];
                g_pre.Qeff[t][l][g] = Qm[l][g] * inv_lam;
            }
        g_pre.its[t] = SCALE_C / expf(fmaxf(tausp[t], 0.f));
        for (int bb = 0; bb < 2; bb++)
            h1[bb][t] = fmaxf(fmaf(sigma[bb] * 20.f - 2.f, w1[t], b1[t]), 0.f);
    }
    __syncthreads();
    if (t < F_)
        for (int bb = 0; bb < 2; bb++) {
            float a = b2[t];
            for (int j = 0; j < F_; j++) a += h1[bb][j] * w2[j * F_ + t];
            h2[bb][t] = fmaxf(a, 0.f);
        }
    __syncthreads();
    if (t < F_)
        for (int bb = 0; bb < 2; bb++) {
            float a = b3[t];
            for (int j = 0; j < F_; j++) a += h2[bb][j] * w3[j * F_ + t];
            float sc = fmaxf(fmaf(a, 0.05f, sigma[bb]), 0.f) + 1e-9f;
            g_pre.invsc[bb][t] = 1.f / sc;
            g_pre.lscal[bb][t] = lamb_e * sc;
        }
}

// ---------------- fused main kernel (384 threads, fused activation) ----------------
__global__ void __launch_bounds__(THREADS, 1)
mfoe_kernel(const float* __restrict__ xn, const float* __restrict__ Wf,
            const int* __restrict__ niter_p, float* __restrict__ out) {
    extern __shared__ float sm[];
    float* Wf_s = sm + OFF_WF;   // [c][e], e = f*4+g, stride 196
    float* x_s  = sm + OFF_X;    // [c][px], stride 64
    float* buf  = sm + OFF_BUF;  // [e][px], stride 64
    float* Qe_s = sm + OFF_QE;
    float* Qm_s = sm + OFF_QM;
    float* ITS  = sm + OFF_ITS;
    float* ISC  = sm + OFF_ISC;
    float* LSC  = sm + OFF_LSC;

    const int t = threadIdx.x;
    const int pix0 = blockIdx.x * NPIX;
    const int b = pix0 >> 14;
    const int sp0 = pix0 & 16383;
    const float* xnb = xn + (size_t)b * (C_ * 16384) + sp0;
    float* outb = out + (size_t)b * (C_ * 16384) + sp0;

    // load Wf into shared: global [g*48+f][c] -> shared [c][f*4+g]
    for (int i = t; i < GF * C_; i += THREADS) {
        int e = i >> 7, c = i & 127;
        int f = e >> 2, g = e & 3;
        Wf_s[c * WFS + e] = Wf[(g * F_ + f) * C_ + c];
    }
    {
        const float* qe = (const float*)g_pre.Qeff;
        const float* qm = (const float*)g_pre.Qm;
        for (int i = t; i < F_ * 16; i += THREADS) {
            Qe_s[i] = qe[i];
            Qm_s[i] = qm[i];
        }
        if (t < F_) {
            ITS[t] = g_pre.its[t];
            ISC[t] = g_pre.invsc[b][t];
            LSC[t] = g_pre.lscal[b][t];
        }
    }
    for (int i = t; i < C_ * NPIX; i += THREADS) {
        int c = i >> 6, p = i & 63;
        x_s[i] = xnb[c * 16384 + p];
    }
    const float eps_e = g_pre.eps_e;
    const float inv_denom = g_pre.inv_denom;
    const int niter = *niter_p;
    __syncthreads();

    const int pxg = t & 7;
    const int px0 = pxg << 3;              // 8 pixels per thread
    const int fth = t >> 3;                // forward: this thread's filter f (0..47)
    const int cg  = t >> 3;                // backward (t<256): c = cg + 32*k

    for (int it = 0; it < niter; ++it) {
        // ---------- forward + fused activation ----------
        {
            // acc[g][j]: group g, pixel-pair j (px0+2j, px0+2j+1)
            unsigned long long acc[4][4];
#pragma unroll
            for (int g = 0; g < 4; g++)
#pragma unroll
                for (int j = 0; j < 4; j++) acc[g][j] = 0ull;

            const float* xcol = x_s + px0;
            const float* wr0 = Wf_s + fth * 4;
#pragma unroll 4
            for (int c = 0; c < C_; c++) {
                ulonglong2 xv0 = *(const ulonglong2*)(xcol + c * 64);
                ulonglong2 xv1 = *(const ulonglong2*)(xcol + c * 64 + 4);
                float4 w = *(const float4*)(wr0 + c * WFS);
                unsigned long long wp0 = pack2(w.x, w.x);
                unsigned long long wp1 = pack2(w.y, w.y);
                unsigned long long wp2 = pack2(w.z, w.z);
                unsigned long long wp3 = pack2(w.w, w.w);
                fma2(acc[0][0], wp0, xv0.x); fma2(acc[0][1], wp0, xv0.y);
                fma2(acc[0][2], wp0, xv1.x); fma2(acc[0][3], wp0, xv1.y);
                fma2(acc[1][0], wp1, xv0.x); fma2(acc[1][1], wp1, xv0.y);
                fma2(acc[1][2], wp1, xv1.x); fma2(acc[1][3], wp1, xv1.y);
                fma2(acc[2][0], wp2, xv0.x); fma2(acc[2][1], wp2, xv0.y);
                fma2(acc[2][2], wp2, xv1.x); fma2(acc[2][3], wp2, xv1.y);
                fma2(acc[3][0], wp3, xv0.x); fma2(acc[3][1], wp3, xv0.y);
                fma2(acc[3][2], wp3, xv1.x); fma2(acc[3][3], wp3, xv1.y);
            }

            // fused activation: this thread owns all 4 groups of filter fth
            const float isc = ISC[fth];
            const float its = ITS[fth];
            const float ls  = LSC[fth];
            const float* qe = Qe_s + fth * 16;
            const float* qm = Qm_s + fth * 16;
            float vout[4][8];
#pragma unroll
            for (int j = 0; j < 4; j++) {
                float2 a0 = unpack2(acc[0][j]);
                float2 a1 = unpack2(acc[1][j]);
                float2 a2 = unpack2(acc[2][j]);
                float2 a3 = unpack2(acc[3][j]);
#pragma unroll
                for (int h = 0; h < 2; h++) {
                    float xv0 = (h ? a0.y : a0.x) * isc;
                    float xv1 = (h ? a1.y : a1.x) * isc;
                    float xv2 = (h ? a2.y : a2.x) * isc;
                    float xv3 = (h ? a3.y : a3.x) * isc;

                    float gc0, gc1, gc2, gc3;
                    proj4(xv0, xv1, xv2, xv3, gc0, gc1, gc2, gc3);
                    gc0 = fmaf(eps_e, xv0, gc0);
                    gc1 = fmaf(eps_e, xv1, gc1);
                    gc2 = fmaf(eps_e, xv2, gc2);
                    gc3 = fmaf(eps_e, xv3, gc3);

                    float y0 = its * (qe[0] * xv0 + qe[1] * xv1 + qe[2] * xv2 + qe[3] * xv3);
                    float y1 = its * (qe[4] * xv0 + qe[5] * xv1 + qe[6] * xv2 + qe[7] * xv3);
                    float y2 = its * (qe[8] * xv0 + qe[9] * xv1 + qe[10] * xv2 + qe[11] * xv3);
                    float y3 = its * (qe[12] * xv0 + qe[13] * xv1 + qe[14] * xv2 + qe[15] * xv3);

                    float gy0, gy1, gy2, gy3;
                    proj4(y0, y1, y2, y3, gy0, gy1, gy2, gy3);
                    gy0 = fmaf(eps_e, y0, gy0);
                    gy1 = fmaf(eps_e, y1, gy1);
                    gy2 = fmaf(eps_e, y2, gy2);
                    gy3 = fmaf(eps_e, y3, gy3);

                    int p = 2 * j + h;
                    vout[0][p] = ls * (gc0 - SCALE_C * (qm[0] * gy0 + qm[4] * gy1 + qm[8] * gy2 + qm[12] * gy3));
                    vout[1][p] = ls * (gc1 - SCALE_C * (qm[1] * gy0 + qm[5] * gy1 + qm[9] * gy2 + qm[13] * gy3));
                    vout[2][p] = ls * (gc2 - SCALE_C * (qm[2] * gy0 + qm[6] * gy1 + qm[10] * gy2 + qm[14] * gy3));
                    vout[3][p] = ls * (gc3 - SCALE_C * (qm[3] * gy0 + qm[7] * gy1 + qm[11] * gy2 + qm[15] * gy3));
                }
            }
#pragma unroll
            for (int g = 0; g < 4; g++) {
                float* dst = buf + (fth * 4 + g) * 64 + px0;
                *(float4*)(dst) = make_float4(vout[g][0], vout[g][1], vout[g][2], vout[g][3]);
                *(float4*)(dst + 4) = make_float4(vout[g][4], vout[g][5], vout[g][6], vout[g][7]);
            }
        }
        __syncthreads();

        // ---------- backward + update (threads 0..255) ----------
        if (t < 256) {
            unsigned long long bac[4][4];
#pragma unroll
            for (int k = 0; k < 4; k++)
#pragma unroll
                for (int j = 0; j < 4; j++) bac[k][j] = 0ull;

            const float* vcol = buf + px0;
#pragma unroll 1
            for (int q = 0; q < 48; q++) {
                const float* vq = vcol + q * 256;     // 4 rows * 64
                ulonglong2 va[4][2];
#pragma unroll
                for (int i = 0; i < 4; i++) {
                    va[i][0] = *(const ulonglong2*)(vq + i * 64);
                    va[i][1] = *(const ulonglong2*)(vq + i * 64 + 4);
                }
#pragma unroll
                for (int k = 0; k < 4; k++) {
                    float4 w = *(const float4*)(&Wf_s[(cg + 32 * k) * WFS + q * 4]);
                    unsigned long long wp0 = pack2(w.x, w.x);
                    unsigned long long wp1 = pack2(w.y, w.y);
                    unsigned long long wp2 = pack2(w.z, w.z);
                    unsigned long long wp3 = pack2(w.w, w.w);
                    fma2(bac[k][0], wp0, va[0][0].x); fma2(bac[k][1], wp0, va[0][0].y);
                    fma2(bac[k][2], wp0, va[0][1].x); fma2(bac[k][3], wp0, va[0][1].y);
                    fma2(bac[k][0], wp1, va[1][0].x); fma2(bac[k][1], wp1, va[1][0].y);
                    fma2(bac[k][2], wp1, va[1][1].x); fma2(bac[k][3], wp1, va[1][1].y);
                    fma2(bac[k][0], wp2, va[2][0].x); fma2(bac[k][1], wp2, va[2][0].y);
                    fma2(bac[k][2], wp2, va[2][1].x); fma2(bac[k][3], wp2, va[2][1].y);
                    fma2(bac[k][0], wp3, va[3][0].x); fma2(bac[k][1], wp3, va[3][0].y);
                    fma2(bac[k][2], wp3, va[3][1].x); fma2(bac[k][3], wp3, va[3][1].y);
                }
            }
#pragma unroll
            for (int k = 0; k < 4; k++) {
                int c = cg + 32 * k;
                const float* xng = xnb + c * 16384 + px0;
                float4 n0 = *(const float4*)(xng);
                float4 n1 = *(const float4*)(xng + 4);
                float* xr = x_s + c * 64 + px0;
                float4 xo0 = *(float4*)(xr);
                float4 xo1 = *(float4*)(xr + 4);
                float2 a0 = unpack2(bac[k][0]);
                float2 a1 = unpack2(bac[k][1]);
                float2 a2 = unpack2(bac[k][2]);
                float2 a3 = unpack2(bac[k][3]);
                xo0.x = xo0.x - (xo0.x - n0.x + a0.x) * inv_denom;
                xo0.y = xo0.y - (xo0.y - n0.y + a0.y) * inv_denom;
                xo0.z = xo0.z - (xo0.z - n0.z + a1.x) * inv_denom;
                xo0.w = xo0.w - (xo0.w - n0.w + a1.y) * inv_denom;
                xo1.x = xo1.x - (xo1.x - n1.x + a2.x) * inv_denom;
                xo1.y = xo1.y - (xo1.y - n1.y + a2.y) * inv_denom;
                xo1.z = xo1.z - (xo1.z - n1.z + a3.x) * inv_denom;
                xo1.w = xo1.w - (xo1.w - n1.w + a3.y) * inv_denom;
                *(float4*)(xr) = xo0;
                *(float4*)(xr + 4) = xo1;
            }
        }
        __syncthreads();
    }

    for (int i = t; i < C_ * NPIX; i += THREADS) {
        int c = i >> 6, p = i & 63;
        outb[c * 16384 + p] = x_s[i];
    }
}

extern "C" void kernel_launch(void* const* d_in, const int* in_sizes, int n_in,
                              void* d_out, int out_size) {
    const float* xn    = (const float*)d_in[0];
    const float* sigma = (const float*)d_in[1];
    const float* Qp    = (const float*)d_in[2];
    const float* tausp = (const float*)d_in[3];
    const float* lamb  = (const float*)d_in[4];
    const float* epso  = (const float*)d_in[5];
    const float* w1    = (const float*)d_in[6];
    const float* b1    = (const float*)d_in[7];
    const float* w2    = (const float*)d_in[8];
    const float* b2    = (const float*)d_in[9];
    const float* w3    = (const float*)d_in[10];
    const float* b3    = (const float*)d_in[11];
    const float* Wf    = (const float*)d_in[12];
    const int* niter   = (const int*)d_in[13];
    float* out = (float*)d_out;

    cudaFuncSetAttribute(mfoe_kernel, cudaFuncAttributeMaxDynamicSharedMemorySize, SMEM_BYTES);
    precomp_kernel<<<1, 64>>>(sigma, Qp, tausp, lamb, epso, w1, b1, w2, b2, w3, b3);
    mfoe_kernel<<<512, THREADS, SMEM_BYTES>>>(xn, Wf, niter, out);
}

// round 7
// speedup vs baseline: 2.5201x; 2.5201x over previous
#include <cuda_runtime.h>
#include <cuda_bf16.h>
#include <cstdint>

#define F_ 48
#define C_ 128
#define GF 192
#define THREADS 256
#define SCALE_C 0.999f

// ---- smem layout (bytes) ----
#define BFS 136   // Bf row stride in bf16 elems (272B: 16B-mult, odd phase -> conflict-free ldmatrix)
#define BBS 200   // Bb row stride in bf16 elems (400B)
#define OFF_BFH 0
#define OFF_BFL (OFF_BFH + GF*BFS*2)      // 52224
#define OFF_BBH (OFF_BFL + GF*BFS*2)      // 104448
#define OFF_BBL (OFF_BBH + C_*BBS*2)      // 155648
#define OFF_QE  (OFF_BBL + C_*BBS*2)      // 206848
#define OFF_QM  (OFF_QE + 3072)           // 209920
#define SMEM_BYTES (OFF_QM + 3072)        // 212992

struct Precomp {
    float Qeff[F_][4][4];
    float Qm[F_][4][4];
    float its[F_];
    float invsc[2][F_];
    float lscal[2][F_];
    float eps_e;
    float inv_denom;
};
__device__ Precomp g_pre;

__device__ __forceinline__ uint32_t smem_u32(const void* p) {
    uint32_t a;
    asm("{ .reg .u64 t; cvta.to.shared.u64 t, %1; cvt.u32.u64 %0, t; }" : "=r"(a) : "l"(p));
    return a;
}
__device__ __forceinline__ float bfr(float v) { return __bfloat162float(__float2bfloat16(v)); }
// pack: a -> low 16 bits (even index), b -> high
__device__ __forceinline__ uint32_t packbf(float a, float b) {
    uint32_t r;
    asm("cvt.rn.bf16x2.f32 %0, %1, %2;" : "=r"(r) : "f"(b), "f"(a));
    return r;
}
__device__ __forceinline__ void ldsm4(uint32_t* r, uint32_t addr) {
    asm volatile("ldmatrix.sync.aligned.m8n8.x4.shared.b16 {%0,%1,%2,%3}, [%4];"
                 : "=r"(r[0]), "=r"(r[1]), "=r"(r[2]), "=r"(r[3]) : "r"(addr));
}
__device__ __forceinline__ void mma16816(float* d, const uint32_t* a, const uint32_t* b) {
    asm volatile(
        "mma.sync.aligned.m16n8k16.row.col.f32.bf16.bf16.f32 "
        "{%0,%1,%2,%3}, {%4,%5,%6,%7}, {%8,%9}, {%0,%1,%2,%3};"
        : "+f"(d[0]), "+f"(d[1]), "+f"(d[2]), "+f"(d[3])
        : "r"(a[0]), "r"(a[1]), "r"(a[2]), "r"(a[3]), "r"(b[0]), "r"(b[1]));
}

__device__ __forceinline__ void proj4(float x0, float x1, float x2, float x3,
                                      float& o0, float& o1, float& o2, float& o3) {
    float a0 = fabsf(x0), a1 = fabsf(x1), a2 = fabsf(x2), a3 = fabsf(x3);
    float ssum = a0 + a1 + a2 + a3;
    float m01 = fmaxf(a0, a1), n01 = fminf(a0, a1);
    float m23 = fmaxf(a2, a3), n23 = fminf(a2, a3);
    float s0 = fmaxf(m01, m23), lo0 = fminf(m01, m23);
    float hi1 = fmaxf(n01, n23), s3 = fminf(n01, n23);
    float s1 = fmaxf(lo0, hi1), s2 = fminf(lo0, hi1);
    float c1 = s0 - 1.f, c2 = c1 + s1, c3 = c2 + s2, c4 = c3 + s3;
    int rho = 1 + (s1 * 2.f > c2) + (s2 * 3.f > c3) + (s3 * 4.f > c4);
    float num = (rho == 1) ? c1 : (rho == 2) ? c2 : (rho == 3) ? c3 : c4;
    float theta = fmaxf(num / (float)rho, 0.f);
    theta = (ssum <= 1.f) ? 0.f : theta;
    o0 = copysignf(fmaxf(a0 - theta, 0.f), x0);
    o1 = copysignf(fmaxf(a1 - theta, 0.f), x1);
    o2 = copysignf(fmaxf(a2 - theta, 0.f), x2);
    o3 = copysignf(fmaxf(a3 - theta, 0.f), x3);
}

// ---------------- precompute kernel (unchanged math) ----------------
__global__ void precomp_kernel(const float* __restrict__ sigma, const float* __restrict__ Qp,
                               const float* __restrict__ tausp, const float* __restrict__ lambp,
                               const float* __restrict__ epsp,
                               const float* __restrict__ w1, const float* __restrict__ b1,
                               const float* __restrict__ w2, const float* __restrict__ b2,
                               const float* __restrict__ w3, const float* __restrict__ b3) {
    __shared__ float h1[2][F_], h2[2][F_];
    int t = threadIdx.x;
    float lamb_e = expf(lambp[0]);
    float eps_e = expf(epsp[0]);
    if (t == 0) {
        g_pre.eps_e = eps_e;
        g_pre.inv_denom = 1.f / (1.f + lamb_e * (1.f + eps_e));
    }
    if (t < F_) {
        float Qm[4][4];
#pragma unroll
        for (int l = 0; l < 4; l++) {
            float rs = 0.f;
#pragma unroll
            for (int g = 0; g < 4; g++) rs += fabsf(Qp[t * 16 + l * 4 + g]);
            float inv = 1.f / fmaxf(rs, 1.f);
#pragma unroll
            for (int g = 0; g < 4; g++) Qm[l][g] = Qp[t * 16 + l * 4 + g] * inv;
        }
        double S[4][4];
        for (int i = 0; i < 4; i++)
            for (int j = 0; j < 4; j++) {
                double acc = 0.0;
                for (int l = 0; l < 4; l++) acc += (double)Qm[l][i] * (double)Qm[l][j];
                S[i][j] = acc;
            }
        const int JP[6] = {0, 0, 0, 1, 1, 2};
        const int JQ[6] = {1, 2, 3, 2, 3, 3};
        for (int sw = 0; sw < 25; sw++)
            for (int rr = 0; rr < 6; rr++) {
                int p = JP[rr], qq = JQ[rr];
                double apq = S[p][qq];
                if (fabs(apq) < 1e-30) continue;
                double th = (S[qq][qq] - S[p][p]) / (2.0 * apq);
                double tt = (th >= 0.0 ? 1.0 : -1.0) / (fabs(th) + sqrt(1.0 + th * th));
                double cc = 1.0 / sqrt(1.0 + tt * tt), ss = tt * cc;
                for (int k = 0; k < 4; k++) {
                    double skp = S[k][p], skq = S[k][qq];
                    S[k][p] = cc * skp - ss * skq;
                    S[k][qq] = ss * skp + cc * skq;
                }
                for (int k = 0; k < 4; k++) {
                    double spk = S[p][k], sqk = S[qq][k];
                    S[p][k] = cc * spk - ss * sqk;
                    S[qq][k] = ss * spk + cc * sqk;
                }
            }
        double lam = S[0][0];
        for (int i = 1; i < 4; i++) lam = (S[i][i] > lam) ? S[i][i] : lam;
        float inv_lam = (float)(1.0 / lam);
#pragma unroll
        for (int l = 0; l < 4; l++)
#pragma unroll
            for (int g = 0; g < 4; g++) {
                g_pre.Qm[t][l][g] = Qm[l][g];
                g_pre.Qeff[t][l][g] = Qm[l][g] * inv_lam;
            }
        g_pre.its[t] = SCALE_C / expf(fmaxf(tausp[t], 0.f));
        for (int bb = 0; bb < 2; bb++)
            h1[bb][t] = fmaxf(fmaf(sigma[bb] * 20.f - 2.f, w1[t], b1[t]), 0.f);
    }
    __syncthreads();
    if (t < F_)
        for (int bb = 0; bb < 2; bb++) {
            float a = b2[t];
            for (int j = 0; j < F_; j++) a += h1[bb][j] * w2[j * F_ + t];
            h2[bb][t] = fmaxf(a, 0.f);
        }
    __syncthreads();
    if (t < F_)
        for (int bb = 0; bb < 2; bb++) {
            float a = b3[t];
            for (int j = 0; j < F_; j++) a += h2[bb][j] * w3[j * F_ + t];
            float sc = fmaxf(fmaf(a, 0.05f, sigma[bb]), 0.f) + 1e-9f;
            g_pre.invsc[bb][t] = 1.f / sc;
            g_pre.lscal[bb][t] = lamb_e * sc;
        }
}

// ---------------- HMMA main kernel: 8 warps x 16-px strips, no mainloop barriers ----------------
__global__ void __launch_bounds__(THREADS, 1)
mfoe_kernel(const float* __restrict__ xn, const float* __restrict__ Wf,
            const int* __restrict__ niter_p, float* __restrict__ out) {
    extern __shared__ char smc[];
    const uint32_t smb = smem_u32(smc);
    const int t = threadIdx.x;
    const int warp = t >> 5, lane = t & 31;
    const int r = lane >> 2, q = lane & 3;
    const int t8 = lane & 7, tb = lane >> 3;

    const int pix0 = blockIdx.x * 128;
    const int b = pix0 >> 14;
    const int sp0 = pix0 & 16383;
    const float* xnw = xn + (size_t)b * (C_ * 16384) + sp0 + warp * 16 + r;
    float* outw = out + (size_t)b * (C_ * 16384) + sp0 + warp * 16 + r;

    // ---- fill weight tiles (scaling folded in) ----
    {
        const float* iscp = g_pre.invsc[b];
        const float* lsp  = g_pre.lscal[b];
        __nv_bfloat16* bfh = (__nv_bfloat16*)(smc + OFF_BFH);
        __nv_bfloat16* bfl = (__nv_bfloat16*)(smc + OFF_BFL);
        __nv_bfloat16* bbh = (__nv_bfloat16*)(smc + OFF_BBH);
        __nv_bfloat16* bbl = (__nv_bfloat16*)(smc + OFF_BBL);
        for (int i = t; i < GF * C_; i += THREADS) {
            int e = i >> 7, c = i & 127;
            int f = e % 48;
            float w = Wf[i];
            float wf = w * iscp[f];
            __nv_bfloat16 h = __float2bfloat16(wf);
            bfh[e * BFS + c] = h;
            bfl[e * BFS + c] = __float2bfloat16(wf - __bfloat162float(h));
            float wb = w * lsp[f];
            __nv_bfloat16 h2 = __float2bfloat16(wb);
            bbh[c * BBS + e] = h2;
            bbl[c * BBS + e] = __float2bfloat16(wb - __bfloat162float(h2));
        }
        float* qes = (float*)(smc + OFF_QE);
        float* qms = (float*)(smc + OFF_QM);
        for (int i = t; i < 768; i += THREADS) {
            qes[i] = ((const float*)g_pre.Qeff)[i] * g_pre.its[i >> 4];
            qms[i] = ((const float*)g_pre.Qm)[i] * SCALE_C;
        }
    }
    __syncthreads();

    const float eps_e = g_pre.eps_e;
    const float inv_denom = g_pre.inv_denom;
    const int niter = *niter_p;
    const float* qes = (const float*)(smc + OFF_QE);
    const float* qms = (const float*)(smc + OFF_QM);

    // ---- x state in registers, D_b fragment layout: x[n][{(r,c0),(r,c0+1),(r+8,c0),(r+8,c0+1)}] ----
    float x[16][4];
#pragma unroll
    for (int n = 0; n < 16; n++) {
        int c0 = 8 * n + 2 * q;
        x[n][0] = xnw[(size_t)c0 * 16384];
        x[n][1] = xnw[(size_t)(c0 + 1) * 16384];
        x[n][2] = xnw[(size_t)c0 * 16384 + 8];
        x[n][3] = xnw[(size_t)(c0 + 1) * 16384 + 8];
    }

    for (int it = 0; it < niter; ++it) {
        // ================= forward: D_f[px][e] = x^T @ BfT =================
        float Df[24][4];
#pragma unroll
        for (int n = 0; n < 24; n++) { Df[n][0] = 0.f; Df[n][1] = 0.f; Df[n][2] = 0.f; Df[n][3] = 0.f; }

#pragma unroll
        for (int jp = 0; jp < 4; jp++) {       // k-step pairs over c
            uint32_t Ah[2][4], Al[2][4];
#pragma unroll
            for (int s = 0; s < 2; s++) {
#pragma unroll
                for (int half = 0; half < 2; half++) {
                    const float* xv = x[4 * jp + 2 * s + half];
                    Ah[s][2 * half + 0] = packbf(xv[0], xv[1]);
                    Ah[s][2 * half + 1] = packbf(xv[2], xv[3]);
                    Al[s][2 * half + 0] = packbf(xv[0] - bfr(xv[0]), xv[1] - bfr(xv[1]));
                    Al[s][2 * half + 1] = packbf(xv[2] - bfr(xv[2]), xv[3] - bfr(xv[3]));
                }
            }
            uint32_t rowoff = smb + OFF_BFH + (uint32_t)(t8 * BFS + 32 * jp + 8 * tb) * 2;
#pragma unroll
            for (int n = 0; n < 24; n++) {
                uint32_t addr = rowoff + (uint32_t)(8 * n * BFS) * 2;
                uint32_t bh[4], bl[4];
                ldsm4(bh, addr);
                ldsm4(bl, addr + (OFF_BFL - OFF_BFH));
                mma16816(Df[n], Ah[0], bh);
                mma16816(Df[n], Al[0], bh);
                mma16816(Df[n], Ah[0], bl);
                mma16816(Df[n], Ah[1], bh + 2);
                mma16816(Df[n], Al[1], bh + 2);
                mma16816(Df[n], Ah[1], bl + 2);
            }
        }

        // ================= activation (register-local, no shuffles) =================
        uint32_t vh[24][2], vl[24][2];
#pragma unroll
        for (int r6 = 0; r6 < 6; r6++) {
            float vt[2][2][4];   // [h][fcol][g]
#pragma unroll
            for (int fcol = 0; fcol < 2; fcol++) {
                int f = 8 * r6 + 2 * q + fcol;
                float4 qe0 = *(const float4*)(qes + f * 16);
                float4 qe1 = *(const float4*)(qes + f * 16 + 4);
                float4 qe2 = *(const float4*)(qes + f * 16 + 8);
                float4 qe3 = *(const float4*)(qes + f * 16 + 12);
                float4 qm0 = *(const float4*)(qms + f * 16);
                float4 qm1 = *(const float4*)(qms + f * 16 + 4);
                float4 qm2 = *(const float4*)(qms + f * 16 + 8);
                float4 qm3 = *(const float4*)(qms + f * 16 + 12);
#pragma unroll
                for (int h = 0; h < 2; h++) {
                    int di = 2 * h + fcol;
                    float xv0 = Df[r6][di], xv1 = Df[r6 + 6][di];
                    float xv2 = Df[r6 + 12][di], xv3 = Df[r6 + 18][di];

                    float gc0, gc1, gc2, gc3;
                    proj4(xv0, xv1, xv2, xv3, gc0, gc1, gc2, gc3);
                    gc0 = fmaf(eps_e, xv0, gc0);
                    gc1 = fmaf(eps_e, xv1, gc1);
                    gc2 = fmaf(eps_e, xv2, gc2);
                    gc3 = fmaf(eps_e, xv3, gc3);

                    float y0 = qe0.x * xv0 + qe0.y * xv1 + qe0.z * xv2 + qe0.w * xv3;
                    float y1 = qe1.x * xv0 + qe1.y * xv1 + qe1.z * xv2 + qe1.w * xv3;
                    float y2 = qe2.x * xv0 + qe2.y * xv1 + qe2.z * xv2 + qe2.w * xv3;
                    float y3 = qe3.x * xv0 + qe3.y * xv1 + qe3.z * xv2 + qe3.w * xv3;

                    float gy0, gy1, gy2, gy3;
                    proj4(y0, y1, y2, y3, gy0, gy1, gy2, gy3);
                    gy0 = fmaf(eps_e, y0, gy0);
                    gy1 = fmaf(eps_e, y1, gy1);
                    gy2 = fmaf(eps_e, y2, gy2);
                    gy3 = fmaf(eps_e, y3, gy3);

                    vt[h][fcol][0] = gc0 - (qm0.x * gy0 + qm1.x * gy1 + qm2.x * gy2 + qm3.x * gy3);
                    vt[h][fcol][1] = gc1 - (qm0.y * gy0 + qm1.y * gy1 + qm2.y * gy2 + qm3.y * gy3);
                    vt[h][fcol][2] = gc2 - (qm0.z * gy0 + qm1.z * gy1 + qm2.z * gy2 + qm3.z * gy3);
                    vt[h][fcol][3] = gc3 - (qm0.w * gy0 + qm1.w * gy1 + qm2.w * gy2 + qm3.w * gy3);
                }
            }
#pragma unroll
            for (int g = 0; g < 4; g++) {
                int n = r6 + 6 * g;
                float a0 = vt[0][0][g], a1 = vt[0][1][g], a2 = vt[1][0][g], a3 = vt[1][1][g];
                vh[n][0] = packbf(a0, a1);
                vh[n][1] = packbf(a2, a3);
                vl[n][0] = packbf(a0 - bfr(a0), a1 - bfr(a1));
                vl[n][1] = packbf(a2 - bfr(a2), a3 - bfr(a3));
            }
        }

        // ================= backward: D_b[px][c] = v @ Bb, + x update =================
#pragma unroll
        for (int n = 0; n < 16; n++) {
            float acc[4] = {0.f, 0.f, 0.f, 0.f};
            uint32_t addr0 = smb + OFF_BBH + (uint32_t)((8 * n + t8) * BBS + 8 * tb) * 2;
#pragma unroll
            for (int jp = 0; jp < 6; jp++) {
                uint32_t addr = addr0 + (uint32_t)(32 * jp) * 2;
                uint32_t bh[4], bl[4];
                ldsm4(bh, addr);
                ldsm4(bl, addr + (OFF_BBL - OFF_BBH));
                uint32_t Ah0[4] = {vh[4 * jp][0], vh[4 * jp][1], vh[4 * jp + 1][0], vh[4 * jp + 1][1]};
                uint32_t Al0[4] = {vl[4 * jp][0], vl[4 * jp][1], vl[4 * jp + 1][0], vl[4 * jp + 1][1]};
                uint32_t Ah1[4] = {vh[4 * jp + 2][0], vh[4 * jp + 2][1], vh[4 * jp + 3][0], vh[4 * jp + 3][1]};
                uint32_t Al1[4] = {vl[4 * jp + 2][0], vl[4 * jp + 2][1], vl[4 * jp + 3][0], vl[4 * jp + 3][1]};
                mma16816(acc, Ah0, bh);
                mma16816(acc, Al0, bh);
                mma16816(acc, Ah0, bl);
                mma16816(acc, Ah1, bh + 2);
                mma16816(acc, Al1, bh + 2);
                mma16816(acc, Ah1, bl + 2);
            }
            int c0 = 8 * n + 2 * q;
            float n0 = xnw[(size_t)c0 * 16384];
            float n1 = xnw[(size_t)(c0 + 1) * 16384];
            float n2 = xnw[(size_t)c0 * 16384 + 8];
            float n3 = xnw[(size_t)(c0 + 1) * 16384 + 8];
            x[n][0] -= (x[n][0] - n0 + acc[0]) * inv_denom;
            x[n][1] -= (x[n][1] - n1 + acc[1]) * inv_denom;
            x[n][2] -= (x[n][2] - n2 + acc[2]) * inv_denom;
            x[n][3] -= (x[n][3] - n3 + acc[3]) * inv_denom;
        }
    }

    // ---- output ----
#pragma unroll
    for (int n = 0; n < 16; n++) {
        int c0 = 8 * n + 2 * q;
        outw[(size_t)c0 * 16384] = x[n][0];
        outw[(size_t)(c0 + 1) * 16384] = x[n][1];
        outw[(size_t)c0 * 16384 + 8] = x[n][2];
        outw[(size_t)(c0 + 1) * 16384 + 8] = x[n][3];
    }
}

extern "C" void kernel_launch(void* const* d_in, const int* in_sizes, int n_in,
                              void* d_out, int out_size) {
    const float* xn    = (const float*)d_in[0];
    const float* sigma = (const float*)d_in[1];
    const float* Qp    = (const float*)d_in[2];
    const float* tausp = (const float*)d_in[3];
    const float* lamb  = (const float*)d_in[4];
    const float* epso  = (const float*)d_in[5];
    const float* w1    = (const float*)d_in[6];
    const float* b1    = (const float*)d_in[7];
    const float* w2    = (const float*)d_in[8];
    const float* b2    = (const float*)d_in[9];
    const float* w3    = (const float*)d_in[10];
    const float* b3    = (const float*)d_in[11];
    const float* Wf    = (const float*)d_in[12];
    const int* niter   = (const int*)d_in[13];
    float* out = (float*)d_out;

    cudaFuncSetAttribute(mfoe_kernel, cudaFuncAttributeMaxDynamicSharedMemorySize, SMEM_BYTES);
    precomp_kernel<<<1, 64>>>(sigma, Qp, tausp, lamb, epso, w1, b1, w2, b2, w3, b3);
    mfoe_kernel<<<256, THREADS, SMEM_BYTES>>>(xn, Wf, niter, out);
}

// round 8
// speedup vs baseline: 2.7946x; 1.1089x over previous
#include <cuda_runtime.h>
#include <cuda_bf16.h>
#include <cstdint>

#define F_ 48
#define C_ 128
#define GF 192
#define THREADS 256
#define SCALE_C 0.999f

// ---- smem layout (bytes) ----
#define BFS 136   // Bf row stride in bf16 elems (272B -> conflict-free ldmatrix)
#define BBS 200   // Bb row stride in bf16 elems (400B)
#define OFF_BFH 0
#define OFF_BFL (OFF_BFH + GF*BFS*2)      // 52224
#define OFF_BBH (OFF_BFL + GF*BFS*2)      // 104448
#define OFF_BBL (OFF_BBH + C_*BBS*2)      // 155648
#define OFF_QE  (OFF_BBL + C_*BBS*2)      // 206848
#define OFF_QM  (OFF_QE + 3072)           // 209920
#define SMEM_BYTES (OFF_QM + 3072)        // 212992

struct Precomp {
    float Qeff[F_][4][4];
    float Qm[F_][4][4];
    float its[F_];
    float invsc[2][F_];
    float lscal[2][F_];
    float eps_e;
    float inv_denom;
};
__device__ Precomp g_pre;

__device__ __forceinline__ uint32_t smem_u32(const void* p) {
    uint32_t a;
    asm("{ .reg .u64 t; cvta.to.shared.u64 t, %1; cvt.u32.u64 %0, t; }" : "=r"(a) : "l"(p));
    return a;
}
// pack: a -> low 16 bits, b -> high
__device__ __forceinline__ uint32_t packbf(float a, float b) {
    uint32_t r;
    asm("cvt.rn.bf16x2.f32 %0, %1, %2;" : "=r"(r) : "f"(b), "f"(a));
    return r;
}
__device__ __forceinline__ float2 unpackbf(uint32_t v) {
    float2 r;
    r.x = __uint_as_float(v << 16);
    r.y = __uint_as_float(v & 0xffff0000u);
    return r;
}
__device__ __forceinline__ float bfr(float v) { return __bfloat162float(__float2bfloat16(v)); }
__device__ __forceinline__ void ldsm4(uint32_t* r, uint32_t addr) {
    asm volatile("ldmatrix.sync.aligned.m8n8.x4.shared.b16 {%0,%1,%2,%3}, [%4];"
                 : "=r"(r[0]), "=r"(r[1]), "=r"(r[2]), "=r"(r[3]) : "r"(addr));
}
__device__ __forceinline__ void mma16816(float* d, const uint32_t* a, const uint32_t* b) {
    asm volatile(
        "mma.sync.aligned.m16n8k16.row.col.f32.bf16.bf16.f32 "
        "{%0,%1,%2,%3}, {%4,%5,%6,%7}, {%8,%9}, {%0,%1,%2,%3};"
        : "+f"(d[0]), "+f"(d[1]), "+f"(d[2]), "+f"(d[3])
        : "r"(a[0]), "r"(a[1]), "r"(a[2]), "r"(a[3]), "r"(b[0]), "r"(b[1]));
}

__device__ __forceinline__ void proj4(float x0, float x1, float x2, float x3,
                                      float& o0, float& o1, float& o2, float& o3) {
    float a0 = fabsf(x0), a1 = fabsf(x1), a2 = fabsf(x2), a3 = fabsf(x3);
    float ssum = a0 + a1 + a2 + a3;
    float m01 = fmaxf(a0, a1), n01 = fminf(a0, a1);
    float m23 = fmaxf(a2, a3), n23 = fminf(a2, a3);
    float s0 = fmaxf(m01, m23), lo0 = fminf(m01, m23);
    float hi1 = fmaxf(n01, n23), s3 = fminf(n01, n23);
    float s1 = fmaxf(lo0, hi1), s2 = fminf(lo0, hi1);
    float c1 = s0 - 1.f, c2 = c1 + s1, c3 = c2 + s2, c4 = c3 + s3;
    int rho = 1 + (s1 * 2.f > c2) + (s2 * 3.f > c3) + (s3 * 4.f > c4);
    float num = (rho == 1) ? c1 : (rho == 2) ? c2 : (rho == 3) ? c3 : c4;
    float theta = fmaxf(num / (float)rho, 0.f);
    theta = (ssum <= 1.f) ? 0.f : theta;
    o0 = copysignf(fmaxf(a0 - theta, 0.f), x0);
    o1 = copysignf(fmaxf(a1 - theta, 0.f), x1);
    o2 = copysignf(fmaxf(a2 - theta, 0.f), x2);
    o3 = copysignf(fmaxf(a3 - theta, 0.f), x3);
}

// ---------------- precompute kernel (unchanged) ----------------
__global__ void precomp_kernel(const float* __restrict__ sigma, const float* __restrict__ Qp,
                               const float* __restrict__ tausp, const float* __restrict__ lambp,
                               const float* __restrict__ epsp,
                               const float* __restrict__ w1, const float* __restrict__ b1,
                               const float* __restrict__ w2, const float* __restrict__ b2,
                               const float* __restrict__ w3, const float* __restrict__ b3) {
    __shared__ float h1[2][F_], h2[2][F_];
    int t = threadIdx.x;
    float lamb_e = expf(lambp[0]);
    float eps_e = expf(epsp[0]);
    if (t == 0) {
        g_pre.eps_e = eps_e;
        g_pre.inv_denom = 1.f / (1.f + lamb_e * (1.f + eps_e));
    }
    if (t < F_) {
        float Qm[4][4];
#pragma unroll
        for (int l = 0; l < 4; l++) {
            float rs = 0.f;
#pragma unroll
            for (int g = 0; g < 4; g++) rs += fabsf(Qp[t * 16 + l * 4 + g]);
            float inv = 1.f / fmaxf(rs, 1.f);
#pragma unroll
            for (int g = 0; g < 4; g++) Qm[l][g] = Qp[t * 16 + l * 4 + g] * inv;
        }
        double S[4][4];
        for (int i = 0; i < 4; i++)
            for (int j = 0; j < 4; j++) {
                double acc = 0.0;
                for (int l = 0; l < 4; l++) acc += (double)Qm[l][i] * (double)Qm[l][j];
                S[i][j] = acc;
            }
        const int JP[6] = {0, 0, 0, 1, 1, 2};
        const int JQ[6] = {1, 2, 3, 2, 3, 3};
        for (int sw = 0; sw < 25; sw++)
            for (int rr = 0; rr < 6; rr++) {
                int p = JP[rr], qq = JQ[rr];
                double apq = S[p][qq];
                if (fabs(apq) < 1e-30) continue;
                double th = (S[qq][qq] - S[p][p]) / (2.0 * apq);
                double tt = (th >= 0.0 ? 1.0 : -1.0) / (fabs(th) + sqrt(1.0 + th * th));
                double cc = 1.0 / sqrt(1.0 + tt * tt), ss = tt * cc;
                for (int k = 0; k < 4; k++) {
                    double skp = S[k][p], skq = S[k][qq];
                    S[k][p] = cc * skp - ss * skq;
                    S[k][qq] = ss * skp + cc * skq;
                }
                for (int k = 0; k < 4; k++) {
                    double spk = S[p][k], sqk = S[qq][k];
                    S[p][k] = cc * spk - ss * sqk;
                    S[qq][k] = ss * spk + cc * sqk;
                }
            }
        double lam = S[0][0];
        for (int i = 1; i < 4; i++) lam = (S[i][i] > lam) ? S[i][i] : lam;
        float inv_lam = (float)(1.0 / lam);
#pragma unroll
        for (int l = 0; l < 4; l++)
#pragma unroll
            for (int g = 0; g < 4; g++) {
                g_pre.Qm[t][l][g] = Qm[l][g];
                g_pre.Qeff[t][l][g] = Qm[l][g] * inv_lam;
            }
        g_pre.its[t] = SCALE_C / expf(fmaxf(tausp[t], 0.f));
        for (int bb = 0; bb < 2; bb++)
            h1[bb][t] = fmaxf(fmaf(sigma[bb] * 20.f - 2.f, w1[t], b1[t]), 0.f);
    }
    __syncthreads();
    if (t < F_)
        for (int bb = 0; bb < 2; bb++) {
            float a = b2[t];
            for (int j = 0; j < F_; j++) a += h1[bb][j] * w2[j * F_ + t];
            h2[bb][t] = fmaxf(a, 0.f);
        }
    __syncthreads();
    if (t < F_)
        for (int bb = 0; bb < 2; bb++) {
            float a = b3[t];
            for (int j = 0; j < F_; j++) a += h2[bb][j] * w3[j * F_ + t];
            float sc = fmaxf(fmaf(a, 0.05f, sigma[bb]), 0.f) + 1e-9f;
            g_pre.invsc[bb][t] = 1.f / sc;
            g_pre.lscal[bb][t] = lamb_e * sc;
        }
}

// ---------------- HMMA main kernel: spill-free, interleaved fwd/act/bwd ----------------
__global__ void __launch_bounds__(THREADS, 1)
mfoe_kernel(const float* __restrict__ xn, const float* __restrict__ Wf,
            const int* __restrict__ niter_p, float* __restrict__ out) {
    extern __shared__ char smc[];
    const uint32_t smb = smem_u32(smc);
    const int t = threadIdx.x;
    const int warp = t >> 5, lane = t & 31;
    const int r = lane >> 2, q = lane & 3;
    const int t8 = lane & 7, tb = lane >> 3;

    const int pix0 = blockIdx.x * 128;
    const int b = pix0 >> 14;
    const int sp0 = pix0 & 16383;
    const float* xnw = xn + (size_t)b * (C_ * 16384) + sp0 + warp * 16 + r;
    float* outw = out + (size_t)b * (C_ * 16384) + sp0 + warp * 16 + r;

    // ---- fill weight tiles (scaling folded in) ----
    {
        const float* iscp = g_pre.invsc[b];
        const float* lsp  = g_pre.lscal[b];
        __nv_bfloat16* bfh = (__nv_bfloat16*)(smc + OFF_BFH);
        __nv_bfloat16* bfl = (__nv_bfloat16*)(smc + OFF_BFL);
        __nv_bfloat16* bbh = (__nv_bfloat16*)(smc + OFF_BBH);
        __nv_bfloat16* bbl = (__nv_bfloat16*)(smc + OFF_BBL);
        for (int i = t; i < GF * C_; i += THREADS) {
            int e = i >> 7, c = i & 127;
            int f = e % 48;
            float w = Wf[i];
            float wf = w * iscp[f];
            __nv_bfloat16 h = __float2bfloat16(wf);
            bfh[e * BFS + c] = h;
            bfl[e * BFS + c] = __float2bfloat16(wf - __bfloat162float(h));
            float wb = w * lsp[f];
            __nv_bfloat16 h2 = __float2bfloat16(wb);
            bbh[c * BBS + e] = h2;
            bbl[c * BBS + e] = __float2bfloat16(wb - __bfloat162float(h2));
        }
        float* qes = (float*)(smc + OFF_QE);
        float* qms = (float*)(smc + OFF_QM);
        for (int i = t; i < 768; i += THREADS) {
            qes[i] = ((const float*)g_pre.Qeff)[i] * g_pre.its[i >> 4];
            qms[i] = ((const float*)g_pre.Qm)[i] * SCALE_C;
        }
    }
    __syncthreads();

    const float eps_e = g_pre.eps_e;
    const float inv_denom = g_pre.inv_denom;
    const int niter = *niter_p;
    const float* qes = (const float*)(smc + OFF_QE);
    const float* qms = (const float*)(smc + OFF_QM);

    // ---- x state lives directly as packed bf16 hi/lo A-fragments ----
    // frag m (0..7) covers c-tiles 2m, 2m+1:
    //   Ahs[m][0] = pack(x[2m][0], x[2m][1])   (row r,    c0, c0+1)
    //   Ahs[m][1] = pack(x[2m][2], x[2m][3])   (row r+8)
    //   Ahs[m][2..3] = same for tile 2m+1
    uint32_t Ahs[8][4], Als[8][4];
#pragma unroll
    for (int n = 0; n < 16; n++) {
        int c0 = 8 * n + 2 * q;
        float x0 = xnw[(size_t)c0 * 16384];
        float x1 = xnw[(size_t)(c0 + 1) * 16384];
        float x2 = xnw[(size_t)c0 * 16384 + 8];
        float x3 = xnw[(size_t)(c0 + 1) * 16384 + 8];
        int m = n >> 1, base = (n & 1) * 2;
        Ahs[m][base] = packbf(x0, x1);
        float2 h0 = unpackbf(Ahs[m][base]);
        Als[m][base] = packbf(x0 - h0.x, x1 - h0.y);
        Ahs[m][base + 1] = packbf(x2, x3);
        float2 h1 = unpackbf(Ahs[m][base + 1]);
        Als[m][base + 1] = packbf(x2 - h1.x, x3 - h1.y);
    }

    for (int it = 0; it < niter; ++it) {
        float acc[16][4];
#pragma unroll
        for (int n = 0; n < 16; n++) { acc[n][0] = 0.f; acc[n][1] = 0.f; acc[n][2] = 0.f; acc[n][3] = 0.f; }

#pragma unroll 1
        for (int r6 = 0; r6 < 6; r6++) {
            // ---- forward quad: Df tiles {r6, r6+6, r6+12, r6+18} ----
            float Df[4][4];
#pragma unroll
            for (int g = 0; g < 4; g++) { Df[g][0] = 0.f; Df[g][1] = 0.f; Df[g][2] = 0.f; Df[g][3] = 0.f; }
#pragma unroll
            for (int jp = 0; jp < 4; jp++) {
                uint32_t rowoff = smb + OFF_BFH + (uint32_t)(t8 * BFS + 32 * jp + 8 * tb) * 2;
#pragma unroll
                for (int g = 0; g < 4; g++) {
                    int n = r6 + 6 * g;
                    uint32_t addr = rowoff + (uint32_t)(8 * n * BFS) * 2;
                    uint32_t bh[4], bl[4];
                    ldsm4(bh, addr);
                    ldsm4(bl, addr + (OFF_BFL - OFF_BFH));
                    mma16816(Df[g], Ahs[2 * jp], bh);
                    mma16816(Df[g], Als[2 * jp], bh);
                    mma16816(Df[g], Ahs[2 * jp], bl);
                    mma16816(Df[g], Ahs[2 * jp + 1], bh + 2);
                    mma16816(Df[g], Als[2 * jp + 1], bh + 2);
                    mma16816(Df[g], Ahs[2 * jp + 1], bl + 2);
                }
            }

            // ---- activation on the quad -> v tiles (packed) ----
            uint32_t vh[4][2], vl[4][2];
            {
                float vt[2][2][4];   // [h][fcol][g]
#pragma unroll
                for (int fcol = 0; fcol < 2; fcol++) {
                    int f = 8 * r6 + 2 * q + fcol;
                    float4 qe0 = *(const float4*)(qes + f * 16);
                    float4 qe1 = *(const float4*)(qes + f * 16 + 4);
                    float4 qe2 = *(const float4*)(qes + f * 16 + 8);
                    float4 qe3 = *(const float4*)(qes + f * 16 + 12);
                    float4 qm0 = *(const float4*)(qms + f * 16);
                    float4 qm1 = *(const float4*)(qms + f * 16 + 4);
                    float4 qm2 = *(const float4*)(qms + f * 16 + 8);
                    float4 qm3 = *(const float4*)(qms + f * 16 + 12);
#pragma unroll
                    for (int h = 0; h < 2; h++) {
                        int di = 2 * h + fcol;
                        float xv0 = Df[0][di], xv1 = Df[1][di];
                        float xv2 = Df[2][di], xv3 = Df[3][di];

                        float gc0, gc1, gc2, gc3;
                        proj4(xv0, xv1, xv2, xv3, gc0, gc1, gc2, gc3);
                        gc0 = fmaf(eps_e, xv0, gc0);
                        gc1 = fmaf(eps_e, xv1, gc1);
                        gc2 = fmaf(eps_e, xv2, gc2);
                        gc3 = fmaf(eps_e, xv3, gc3);

                        float y0 = qe0.x * xv0 + qe0.y * xv1 + qe0.z * xv2 + qe0.w * xv3;
                        float y1 = qe1.x * xv0 + qe1.y * xv1 + qe1.z * xv2 + qe1.w * xv3;
                        float y2 = qe2.x * xv0 + qe2.y * xv1 + qe2.z * xv2 + qe2.w * xv3;
                        float y3 = qe3.x * xv0 + qe3.y * xv1 + qe3.z * xv2 + qe3.w * xv3;

                        float gy0, gy1, gy2, gy3;
                        proj4(y0, y1, y2, y3, gy0, gy1, gy2, gy3);
                        gy0 = fmaf(eps_e, y0, gy0);
                        gy1 = fmaf(eps_e, y1, gy1);
                        gy2 = fmaf(eps_e, y2, gy2);
                        gy3 = fmaf(eps_e, y3, gy3);

                        vt[h][fcol][0] = gc0 - (qm0.x * gy0 + qm1.x * gy1 + qm2.x * gy2 + qm3.x * gy3);
                        vt[h][fcol][1] = gc1 - (qm0.y * gy0 + qm1.y * gy1 + qm2.y * gy2 + qm3.y * gy3);
                        vt[h][fcol][2] = gc2 - (qm0.z * gy0 + qm1.z * gy1 + qm2.z * gy2 + qm3.z * gy3);
                        vt[h][fcol][3] = gc3 - (qm0.w * gy0 + qm1.w * gy1 + qm2.w * gy2 + qm3.w * gy3);
                    }
                }
#pragma unroll
                for (int g = 0; g < 4; g++) {
                    float a0 = vt[0][0][g], a1 = vt[0][1][g], a2 = vt[1][0][g], a3 = vt[1][1][g];
                    vh[g][0] = packbf(a0, a1);
                    vh[g][1] = packbf(a2, a3);
                    vl[g][0] = packbf(a0 - bfr(a0), a1 - bfr(a1));
                    vl[g][1] = packbf(a2 - bfr(a2), a3 - bfr(a3));
                }
            }

            // ---- backward partial: consume v tiles at e-tiles {r6+6*tb} ----
            uint32_t Ah0[4] = {vh[0][0], vh[0][1], vh[1][0], vh[1][1]};
            uint32_t Al0[4] = {vl[0][0], vl[0][1], vl[1][0], vl[1][1]};
            uint32_t Ah1[4] = {vh[2][0], vh[2][1], vh[3][0], vh[3][1]};
            uint32_t Al1[4] = {vl[2][0], vl[2][1], vl[3][0], vl[3][1]};
            uint32_t bwdoff = smb + OFF_BBH + (uint32_t)(t8 * BBS + 8 * r6 + 48 * tb) * 2;
#pragma unroll
            for (int n = 0; n < 16; n++) {
                uint32_t addr = bwdoff + (uint32_t)(8 * n * BBS) * 2;
                uint32_t bh[4], bl[4];
                ldsm4(bh, addr);
                ldsm4(bl, addr + (OFF_BBL - OFF_BBH));
                mma16816(acc[n], Ah0, bh);
                mma16816(acc[n], Al0, bh);
                mma16816(acc[n], Ah0, bl);
                mma16816(acc[n], Ah1, bh + 2);
                mma16816(acc[n], Al1, bh + 2);
                mma16816(acc[n], Ah1, bl + 2);
            }
        }

        // ---- update x state (reconstruct, step, repack) ----
#pragma unroll
        for (int n = 0; n < 16; n++) {
            int c0 = 8 * n + 2 * q;
            float n0 = xnw[(size_t)c0 * 16384];
            float n1 = xnw[(size_t)(c0 + 1) * 16384];
            float n2 = xnw[(size_t)c0 * 16384 + 8];
            float n3 = xnw[(size_t)(c0 + 1) * 16384 + 8];
            int m = n >> 1, base = (n & 1) * 2;
            float2 h0 = unpackbf(Ahs[m][base]);
            float2 h1 = unpackbf(Ahs[m][base + 1]);
            float2 l0 = unpackbf(Als[m][base]);
            float2 l1 = unpackbf(Als[m][base + 1]);
            float x0 = h0.x + l0.x, x1 = h0.y + l0.y;
            float x2 = h1.x + l1.x, x3 = h1.y + l1.y;
            x0 -= (x0 - n0 + acc[n][0]) * inv_denom;
            x1 -= (x1 - n1 + acc[n][1]) * inv_denom;
            x2 -= (x2 - n2 + acc[n][2]) * inv_denom;
            x3 -= (x3 - n3 + acc[n][3]) * inv_denom;
            Ahs[m][base] = packbf(x0, x1);
            float2 nh0 = unpackbf(Ahs[m][base]);
            Als[m][base] = packbf(x0 - nh0.x, x1 - nh0.y);
            Ahs[m][base + 1] = packbf(x2, x3);
            float2 nh1 = unpackbf(Ahs[m][base + 1]);
            Als[m][base + 1] = packbf(x2 - nh1.x, x3 - nh1.y);
        }
    }

    // ---- output: reconstruct and store ----
#pragma unroll
    for (int n = 0; n < 16; n++) {
        int c0 = 8 * n + 2 * q;
        int m = n >> 1, base = (n & 1) * 2;
        float2 h0 = unpackbf(Ahs[m][base]);
        float2 h1 = unpackbf(Ahs[m][base + 1]);
        float2 l0 = unpackbf(Als[m][base]);
        float2 l1 = unpackbf(Als[m][base + 1]);
        outw[(size_t)c0 * 16384] = h0.x + l0.x;
        outw[(size_t)(c0 + 1) * 16384] = h0.y + l0.y;
        outw[(size_t)c0 * 16384 + 8] = h1.x + l1.x;
        outw[(size_t)(c0 + 1) * 16384 + 8] = h1.y + l1.y;
    }
}

extern "C" void kernel_launch(void* const* d_in, const int* in_sizes, int n_in,
                              void* d_out, int out_size) {
    const float* xn    = (const float*)d_in[0];
    const float* sigma = (const float*)d_in[1];
    const float* Qp    = (const float*)d_in[2];
    const float* tausp = (const float*)d_in[3];
    const float* lamb  = (const float*)d_in[4];
    const float* epso  = (const float*)d_in[5];
    const float* w1    = (const float*)d_in[6];
    const float* b1    = (const float*)d_in[7];
    const float* w2    = (const float*)d_in[8];
    const float* b2    = (const float*)d_in[9];
    const float* w3    = (const float*)d_in[10];
    const float* b3    = (const float*)d_in[11];
    const float* Wf    = (const float*)d_in[12];
    const int* niter   = (const int*)d_in[13];
    float* out = (float*)d_out;

    cudaFuncSetAttribute(mfoe_kernel, cudaFuncAttributeMaxDynamicSharedMemorySize, SMEM_BYTES);
    precomp_kernel<<<1, 64>>>(sigma, Qp, tausp, lamb, epso, w1, b1, w2, b2, w3, b3);
    mfoe_kernel<<<256, THREADS, SMEM_BYTES>>>(xn, Wf, niter, out);
}

// round 9
// speedup vs baseline: 2.9934x; 1.0711x over previous
#include <cuda_runtime.h>
#include <cuda_bf16.h>
#include <cstdint>

#define F_ 48
#define C_ 128
#define GF 192
#define THREADS 256
#define SCALE_C 0.999f

// ---- smem layout (bytes) ----
#define BFS 136   // Bf row stride in bf16 elems (272B -> conflict-free ldmatrix)
#define BBS 200   // Bb row stride in bf16 elems (400B)
#define OFF_BFH 0
#define OFF_BFL (OFF_BFH + GF*BFS*2)      // 52224
#define OFF_BBH (OFF_BFL + GF*BFS*2)      // 104448  (hi only; bwd is 2-term)
#define OFF_QE  (OFF_BBH + C_*BBS*2)      // 155648
#define OFF_QM  (OFF_QE + 3072)           // 158720
#define SMEM_BYTES (OFF_QM + 3072)        // 161792

struct Precomp {
    float Qeff[F_][4][4];
    float Qm[F_][4][4];
    float its[F_];
    float invsc[2][F_];
    float lscal[2][F_];
    float eps_e;
    float inv_denom;
};
__device__ Precomp g_pre;

__device__ __forceinline__ uint32_t smem_u32(const void* p) {
    uint32_t a;
    asm("{ .reg .u64 t; cvta.to.shared.u64 t, %1; cvt.u32.u64 %0, t; }" : "=r"(a) : "l"(p));
    return a;
}
// pack: a -> low 16 bits, b -> high
__device__ __forceinline__ uint32_t packbf(float a, float b) {
    uint32_t r;
    asm("cvt.rn.bf16x2.f32 %0, %1, %2;" : "=r"(r) : "f"(b), "f"(a));
    return r;
}
__device__ __forceinline__ float2 unpackbf(uint32_t v) {
    float2 r;
    r.x = __uint_as_float(v << 16);
    r.y = __uint_as_float(v & 0xffff0000u);
    return r;
}
__device__ __forceinline__ float bfr(float v) { return __bfloat162float(__float2bfloat16(v)); }
__device__ __forceinline__ void ldsm4(uint32_t* r, uint32_t addr) {
    asm volatile("ldmatrix.sync.aligned.m8n8.x4.shared.b16 {%0,%1,%2,%3}, [%4];"
                 : "=r"(r[0]), "=r"(r[1]), "=r"(r[2]), "=r"(r[3]) : "r"(addr));
}
__device__ __forceinline__ void mma16816(float* d, const uint32_t* a, const uint32_t* b) {
    asm volatile(
        "mma.sync.aligned.m16n8k16.row.col.f32.bf16.bf16.f32 "
        "{%0,%1,%2,%3}, {%4,%5,%6,%7}, {%8,%9}, {%0,%1,%2,%3};"
        : "+f"(d[0]), "+f"(d[1]), "+f"(d[2]), "+f"(d[3])
        : "r"(a[0]), "r"(a[1]), "r"(a[2]), "r"(a[3]), "r"(b[0]), "r"(b[1]));
}

__device__ __forceinline__ void proj4(float x0, float x1, float x2, float x3,
                                      float& o0, float& o1, float& o2, float& o3) {
    float a0 = fabsf(x0), a1 = fabsf(x1), a2 = fabsf(x2), a3 = fabsf(x3);
    float ssum = a0 + a1 + a2 + a3;
    float m01 = fmaxf(a0, a1), n01 = fminf(a0, a1);
    float m23 = fmaxf(a2, a3), n23 = fminf(a2, a3);
    float s0 = fmaxf(m01, m23), lo0 = fminf(m01, m23);
    float hi1 = fmaxf(n01, n23), s3 = fminf(n01, n23);
    float s1 = fmaxf(lo0, hi1), s2 = fminf(lo0, hi1);
    float c1 = s0 - 1.f, c2 = c1 + s1, c3 = c2 + s2, c4 = c3 + s3;
    int rho = 1 + (s1 * 2.f > c2) + (s2 * 3.f > c3) + (s3 * 4.f > c4);
    float num = (rho == 1) ? c1 : (rho == 2) ? c2 : (rho == 3) ? c3 : c4;
    float theta = fmaxf(num / (float)rho, 0.f);
    theta = (ssum <= 1.f) ? 0.f : theta;
    o0 = copysignf(fmaxf(a0 - theta, 0.f), x0);
    o1 = copysignf(fmaxf(a1 - theta, 0.f), x1);
    o2 = copysignf(fmaxf(a2 - theta, 0.f), x2);
    o3 = copysignf(fmaxf(a3 - theta, 0.f), x3);
}

// ---------------- precompute kernel (unchanged) ----------------
__global__ void precomp_kernel(const float* __restrict__ sigma, const float* __restrict__ Qp,
                               const float* __restrict__ tausp, const float* __restrict__ lambp,
                               const float* __restrict__ epsp,
                               const float* __restrict__ w1, const float* __restrict__ b1,
                               const float* __restrict__ w2, const float* __restrict__ b2,
                               const float* __restrict__ w3, const float* __restrict__ b3) {
    __shared__ float h1[2][F_], h2[2][F_];
    int t = threadIdx.x;
    float lamb_e = expf(lambp[0]);
    float eps_e = expf(epsp[0]);
    if (t == 0) {
        g_pre.eps_e = eps_e;
        g_pre.inv_denom = 1.f / (1.f + lamb_e * (1.f + eps_e));
    }
    if (t < F_) {
        float Qm[4][4];
#pragma unroll
        for (int l = 0; l < 4; l++) {
            float rs = 0.f;
#pragma unroll
            for (int g = 0; g < 4; g++) rs += fabsf(Qp[t * 16 + l * 4 + g]);
            float inv = 1.f / fmaxf(rs, 1.f);
#pragma unroll
            for (int g = 0; g < 4; g++) Qm[l][g] = Qp[t * 16 + l * 4 + g] * inv;
        }
        double S[4][4];
        for (int i = 0; i < 4; i++)
            for (int j = 0; j < 4; j++) {
                double acc = 0.0;
                for (int l = 0; l < 4; l++) acc += (double)Qm[l][i] * (double)Qm[l][j];
                S[i][j] = acc;
            }
        const int JP[6] = {0, 0, 0, 1, 1, 2};
        const int JQ[6] = {1, 2, 3, 2, 3, 3};
        for (int sw = 0; sw < 25; sw++)
            for (int rr = 0; rr < 6; rr++) {
                int p = JP[rr], qq = JQ[rr];
                double apq = S[p][qq];
                if (fabs(apq) < 1e-30) continue;
                double th = (S[qq][qq] - S[p][p]) / (2.0 * apq);
                double tt = (th >= 0.0 ? 1.0 : -1.0) / (fabs(th) + sqrt(1.0 + th * th));
                double cc = 1.0 / sqrt(1.0 + tt * tt), ss = tt * cc;
                for (int k = 0; k < 4; k++) {
                    double skp = S[k][p], skq = S[k][qq];
                    S[k][p] = cc * skp - ss * skq;
                    S[k][qq] = ss * skp + cc * skq;
                }
                for (int k = 0; k < 4; k++) {
                    double spk = S[p][k], sqk = S[qq][k];
                    S[p][k] = cc * spk - ss * sqk;
                    S[qq][k] = ss * spk + cc * sqk;
                }
            }
        double lam = S[0][0];
        for (int i = 1; i < 4; i++) lam = (S[i][i] > lam) ? S[i][i] : lam;
        float inv_lam = (float)(1.0 / lam);
#pragma unroll
        for (int l = 0; l < 4; l++)
#pragma unroll
            for (int g = 0; g < 4; g++) {
                g_pre.Qm[t][l][g] = Qm[l][g];
                g_pre.Qeff[t][l][g] = Qm[l][g] * inv_lam;
            }
        g_pre.its[t] = SCALE_C / expf(fmaxf(tausp[t], 0.f));
        for (int bb = 0; bb < 2; bb++)
            h1[bb][t] = fmaxf(fmaf(sigma[bb] * 20.f - 2.f, w1[t], b1[t]), 0.f);
    }
    __syncthreads();
    if (t < F_)
        for (int bb = 0; bb < 2; bb++) {
            float a = b2[t];
            for (int j = 0; j < F_; j++) a += h1[bb][j] * w2[j * F_ + t];
            h2[bb][t] = fmaxf(a, 0.f);
        }
    __syncthreads();
    if (t < F_)
        for (int bb = 0; bb < 2; bb++) {
            float a = b3[t];
            for (int j = 0; j < F_; j++) a += h2[bb][j] * w3[j * F_ + t];
            float sc = fmaxf(fmaf(a, 0.05f, sigma[bb]), 0.f) + 1e-9f;
            g_pre.invsc[bb][t] = 1.f / sc;
            g_pre.lscal[bb][t] = lamb_e * sc;
        }
}

// ---------------- HMMA main kernel: 3-term fwd, 2-term bwd ----------------
__global__ void __launch_bounds__(THREADS, 1)
mfoe_kernel(const float* __restrict__ xn, const float* __restrict__ Wf,
            const int* __restrict__ niter_p, float* __restrict__ out) {
    extern __shared__ char smc[];
    const uint32_t smb = smem_u32(smc);
    const int t = threadIdx.x;
    const int warp = t >> 5, lane = t & 31;
    const int r = lane >> 2, q = lane & 3;
    const int t8 = lane & 7, tb = lane >> 3;

    const int pix0 = blockIdx.x * 128;
    const int b = pix0 >> 14;
    const int sp0 = pix0 & 16383;
    const float* xnw = xn + (size_t)b * (C_ * 16384) + sp0 + warp * 16 + r;
    float* outw = out + (size_t)b * (C_ * 16384) + sp0 + warp * 16 + r;

    // ---- fill weight tiles (scaling folded in) ----
    {
        const float* iscp = g_pre.invsc[b];
        const float* lsp  = g_pre.lscal[b];
        __nv_bfloat16* bfh = (__nv_bfloat16*)(smc + OFF_BFH);
        __nv_bfloat16* bfl = (__nv_bfloat16*)(smc + OFF_BFL);
        __nv_bfloat16* bbh = (__nv_bfloat16*)(smc + OFF_BBH);
        for (int i = t; i < GF * C_; i += THREADS) {
            int e = i >> 7, c = i & 127;
            int f = e % 48;
            float w = Wf[i];
            float wf = w * iscp[f];
            __nv_bfloat16 h = __float2bfloat16(wf);
            bfh[e * BFS + c] = h;
            bfl[e * BFS + c] = __float2bfloat16(wf - __bfloat162float(h));
            bbh[c * BBS + e] = __float2bfloat16(w * lsp[f]);
        }
        float* qes = (float*)(smc + OFF_QE);
        float* qms = (float*)(smc + OFF_QM);
        for (int i = t; i < 768; i += THREADS) {
            qes[i] = ((const float*)g_pre.Qeff)[i] * g_pre.its[i >> 4];
            qms[i] = ((const float*)g_pre.Qm)[i] * SCALE_C;
        }
    }
    __syncthreads();

    const float eps_e = g_pre.eps_e;
    const float inv_denom = g_pre.inv_denom;
    const int niter = *niter_p;
    const float* qes = (const float*)(smc + OFF_QE);
    const float* qms = (const float*)(smc + OFF_QM);

    // ---- x state lives directly as packed bf16 hi/lo A-fragments ----
    uint32_t Ahs[8][4], Als[8][4];
#pragma unroll
    for (int n = 0; n < 16; n++) {
        int c0 = 8 * n + 2 * q;
        float x0 = xnw[(size_t)c0 * 16384];
        float x1 = xnw[(size_t)(c0 + 1) * 16384];
        float x2 = xnw[(size_t)c0 * 16384 + 8];
        float x3 = xnw[(size_t)(c0 + 1) * 16384 + 8];
        int m = n >> 1, base = (n & 1) * 2;
        Ahs[m][base] = packbf(x0, x1);
        float2 h0 = unpackbf(Ahs[m][base]);
        Als[m][base] = packbf(x0 - h0.x, x1 - h0.y);
        Ahs[m][base + 1] = packbf(x2, x3);
        float2 h1 = unpackbf(Ahs[m][base + 1]);
        Als[m][base + 1] = packbf(x2 - h1.x, x3 - h1.y);
    }

    for (int it = 0; it < niter; ++it) {
        float acc[16][4];
#pragma unroll
        for (int n = 0; n < 16; n++) { acc[n][0] = 0.f; acc[n][1] = 0.f; acc[n][2] = 0.f; acc[n][3] = 0.f; }

#pragma unroll 1
        for (int r6 = 0; r6 < 6; r6++) {
            // ---- forward quad: Df tiles {r6, r6+6, r6+12, r6+18}, 3-term ----
            float Df[4][4];
#pragma unroll
            for (int g = 0; g < 4; g++) { Df[g][0] = 0.f; Df[g][1] = 0.f; Df[g][2] = 0.f; Df[g][3] = 0.f; }
#pragma unroll
            for (int jp = 0; jp < 4; jp++) {
                uint32_t rowoff = smb + OFF_BFH + (uint32_t)(t8 * BFS + 32 * jp + 8 * tb) * 2;
#pragma unroll
                for (int g = 0; g < 4; g++) {
                    int n = r6 + 6 * g;
                    uint32_t addr = rowoff + (uint32_t)(8 * n * BFS) * 2;
                    uint32_t bh[4], bl[4];
                    ldsm4(bh, addr);
                    ldsm4(bl, addr + (OFF_BFL - OFF_BFH));
                    mma16816(Df[g], Ahs[2 * jp], bh);
                    mma16816(Df[g], Als[2 * jp], bh);
                    mma16816(Df[g], Ahs[2 * jp], bl);
                    mma16816(Df[g], Ahs[2 * jp + 1], bh + 2);
                    mma16816(Df[g], Als[2 * jp + 1], bh + 2);
                    mma16816(Df[g], Ahs[2 * jp + 1], bl + 2);
                }
            }

            // ---- activation on the quad -> v tiles (packed hi/lo) ----
            uint32_t vh[4][2], vl[4][2];
            {
                float vt[2][2][4];   // [h][fcol][g]
#pragma unroll
                for (int fcol = 0; fcol < 2; fcol++) {
                    int f = 8 * r6 + 2 * q + fcol;
                    float4 qe0 = *(const float4*)(qes + f * 16);
                    float4 qe1 = *(const float4*)(qes + f * 16 + 4);
                    float4 qe2 = *(const float4*)(qes + f * 16 + 8);
                    float4 qe3 = *(const float4*)(qes + f * 16 + 12);
                    float4 qm0 = *(const float4*)(qms + f * 16);
                    float4 qm1 = *(const float4*)(qms + f * 16 + 4);
                    float4 qm2 = *(const float4*)(qms + f * 16 + 8);
                    float4 qm3 = *(const float4*)(qms + f * 16 + 12);
#pragma unroll
                    for (int h = 0; h < 2; h++) {
                        int di = 2 * h + fcol;
                        float xv0 = Df[0][di], xv1 = Df[1][di];
                        float xv2 = Df[2][di], xv3 = Df[3][di];

                        float gc0, gc1, gc2, gc3;
                        proj4(xv0, xv1, xv2, xv3, gc0, gc1, gc2, gc3);
                        gc0 = fmaf(eps_e, xv0, gc0);
                        gc1 = fmaf(eps_e, xv1, gc1);
                        gc2 = fmaf(eps_e, xv2, gc2);
                        gc3 = fmaf(eps_e, xv3, gc3);

                        float y0 = qe0.x * xv0 + qe0.y * xv1 + qe0.z * xv2 + qe0.w * xv3;
                        float y1 = qe1.x * xv0 + qe1.y * xv1 + qe1.z * xv2 + qe1.w * xv3;
                        float y2 = qe2.x * xv0 + qe2.y * xv1 + qe2.z * xv2 + qe2.w * xv3;
                        float y3 = qe3.x * xv0 + qe3.y * xv1 + qe3.z * xv2 + qe3.w * xv3;

                        float gy0, gy1, gy2, gy3;
                        proj4(y0, y1, y2, y3, gy0, gy1, gy2, gy3);
                        gy0 = fmaf(eps_e, y0, gy0);
                        gy1 = fmaf(eps_e, y1, gy1);
                        gy2 = fmaf(eps_e, y2, gy2);
                        gy3 = fmaf(eps_e, y3, gy3);

                        vt[h][fcol][0] = gc0 - (qm0.x * gy0 + qm1.x * gy1 + qm2.x * gy2 + qm3.x * gy3);
                        vt[h][fcol][1] = gc1 - (qm0.y * gy0 + qm1.y * gy1 + qm2.y * gy2 + qm3.y * gy3);
                        vt[h][fcol][2] = gc2 - (qm0.z * gy0 + qm1.z * gy1 + qm2.z * gy2 + qm3.z * gy3);
                        vt[h][fcol][3] = gc3 - (qm0.w * gy0 + qm1.w * gy1 + qm2.w * gy2 + qm3.w * gy3);
                    }
                }
#pragma unroll
                for (int g = 0; g < 4; g++) {
                    float a0 = vt[0][0][g], a1 = vt[0][1][g], a2 = vt[1][0][g], a3 = vt[1][1][g];
                    vh[g][0] = packbf(a0, a1);
                    vh[g][1] = packbf(a2, a3);
                    vl[g][0] = packbf(a0 - bfr(a0), a1 - bfr(a1));
                    vl[g][1] = packbf(a2 - bfr(a2), a3 - bfr(a3));
                }
            }

            // ---- backward partial (2-term: exact v  x bf16(W)) ----
            uint32_t Ah0[4] = {vh[0][0], vh[0][1], vh[1][0], vh[1][1]};
            uint32_t Al0[4] = {vl[0][0], vl[0][1], vl[1][0], vl[1][1]};
            uint32_t Ah1[4] = {vh[2][0], vh[2][1], vh[3][0], vh[3][1]};
            uint32_t Al1[4] = {vl[2][0], vl[2][1], vl[3][0], vl[3][1]};
            uint32_t bwdoff = smb + OFF_BBH + (uint32_t)(t8 * BBS + 8 * r6 + 48 * tb) * 2;
#pragma unroll
            for (int n = 0; n < 16; n++) {
                uint32_t addr = bwdoff + (uint32_t)(8 * n * BBS) * 2;
                uint32_t bh[4];
                ldsm4(bh, addr);
                mma16816(acc[n], Ah0, bh);
                mma16816(acc[n], Al0, bh);
                mma16816(acc[n], Ah1, bh + 2);
                mma16816(acc[n], Al1, bh + 2);
            }
        }

        // ---- update x state (reconstruct, step, repack) ----
#pragma unroll
        for (int n = 0; n < 16; n++) {
            int c0 = 8 * n + 2 * q;
            float n0 = xnw[(size_t)c0 * 16384];
            float n1 = xnw[(size_t)(c0 + 1) * 16384];
            float n2 = xnw[(size_t)c0 * 16384 + 8];
            float n3 = xnw[(size_t)(c0 + 1) * 16384 + 8];
            int m = n >> 1, base = (n & 1) * 2;
            float2 h0 = unpackbf(Ahs[m][base]);
            float2 h1 = unpackbf(Ahs[m][base + 1]);
            float2 l0 = unpackbf(Als[m][base]);
            float2 l1 = unpackbf(Als[m][base + 1]);
            float x0 = h0.x + l0.x, x1 = h0.y + l0.y;
            float x2 = h1.x + l1.x, x3 = h1.y + l1.y;
            x0 -= (x0 - n0 + acc[n][0]) * inv_denom;
            x1 -= (x1 - n1 + acc[n][1]) * inv_denom;
            x2 -= (x2 - n2 + acc[n][2]) * inv_denom;
            x3 -= (x3 - n3 + acc[n][3]) * inv_denom;
            Ahs[m][base] = packbf(x0, x1);
            float2 nh0 = unpackbf(Ahs[m][base]);
            Als[m][base] = packbf(x0 - nh0.x, x1 - nh0.y);
            Ahs[m][base + 1] = packbf(x2, x3);
            float2 nh1 = unpackbf(Ahs[m][base + 1]);
            Als[m][base + 1] = packbf(x2 - nh1.x, x3 - nh1.y);
        }
    }

    // ---- output: reconstruct and store ----
#pragma unroll
    for (int n = 0; n < 16; n++) {
        int c0 = 8 * n + 2 * q;
        int m = n >> 1, base = (n & 1) * 2;
        float2 h0 = unpackbf(Ahs[m][base]);
        float2 h1 = unpackbf(Ahs[m][base + 1]);
        float2 l0 = unpackbf(Als[m][base]);
        float2 l1 = unpackbf(Als[m][base + 1]);
        outw[(size_t)c0 * 16384] = h0.x + l0.x;
        outw[(size_t)(c0 + 1) * 16384] = h0.y + l0.y;
        outw[(size_t)c0 * 16384 + 8] = h1.x + l1.x;
        outw[(size_t)(c0 + 1) * 16384 + 8] = h1.y + l1.y;
    }
}

extern "C" void kernel_launch(void* const* d_in, const int* in_sizes, int n_in,
                              void* d_out, int out_size) {
    const float* xn    = (const float*)d_in[0];
    const float* sigma = (const float*)d_in[1];
    const float* Qp    = (const float*)d_in[2];
    const float* tausp = (const float*)d_in[3];
    const float* lamb  = (const float*)d_in[4];
    const float* epso  = (const float*)d_in[5];
    const float* w1    = (const float*)d_in[6];
    const float* b1    = (const float*)d_in[7];
    const float* w2    = (const float*)d_in[8];
    const float* b2    = (const float*)d_in[9];
    const float* w3    = (const float*)d_in[10];
    const float* b3    = (const float*)d_in[11];
    const float* Wf    = (const float*)d_in[12];
    const int* niter   = (const int*)d_in[13];
    float* out = (float*)d_out;

    cudaFuncSetAttribute(mfoe_kernel, cudaFuncAttributeMaxDynamicSharedMemorySize, SMEM_BYTES);
    precomp_kernel<<<1, 64>>>(sigma, Qp, tausp, lamb, epso, w1, b1, w2, b2, w3, b3);
    mfoe_kernel<<<256, THREADS, SMEM_BYTES>>>(xn, Wf, niter, out);
}

// round 10
// speedup vs baseline: 3.0568x; 1.0212x over previous
#include <cuda_runtime.h>
#include <cuda_bf16.h>
#include <cstdint>

#define F_ 48
#define C_ 128
#define GF 192
#define THREADS 256
#define SCALE_C 0.999f

// ---- smem layout (bytes) ----
#define BFS 136   // Bf row stride in bf16 elems (272B -> conflict-free ldmatrix)
#define BBS 200   // Bb row stride in bf16 elems (400B)
#define OFF_BFH 0
#define OFF_BFL (OFF_BFH + GF*BFS*2)      // 52224
#define OFF_BBH (OFF_BFL + GF*BFS*2)      // 104448  (hi only; bwd is 1-term)
#define OFF_QE  (OFF_BBH + C_*BBS*2)      // 155648
#define OFF_QM  (OFF_QE + 3072)           // 158720
#define SMEM_BYTES (OFF_QM + 3072)        // 161792

struct Precomp {
    float Qeff[F_][4][4];
    float Qm[F_][4][4];
    float its[F_];
    float invsc[2][F_];
    float lscal[2][F_];
    float eps_e;
    float inv_denom;
};
__device__ Precomp g_pre;

__device__ __forceinline__ uint32_t smem_u32(const void* p) {
    uint32_t a;
    asm("{ .reg .u64 t; cvta.to.shared.u64 t, %1; cvt.u32.u64 %0, t; }" : "=r"(a) : "l"(p));
    return a;
}
// pack: a -> low 16 bits, b -> high
__device__ __forceinline__ uint32_t packbf(float a, float b) {
    uint32_t r;
    asm("cvt.rn.bf16x2.f32 %0, %1, %2;" : "=r"(r) : "f"(b), "f"(a));
    return r;
}
__device__ __forceinline__ float2 unpackbf(uint32_t v) {
    float2 r;
    r.x = __uint_as_float(v << 16);
    r.y = __uint_as_float(v & 0xffff0000u);
    return r;
}
__device__ __forceinline__ void ldsm4(uint32_t* r, uint32_t addr) {
    asm volatile("ldmatrix.sync.aligned.m8n8.x4.shared.b16 {%0,%1,%2,%3}, [%4];"
                 : "=r"(r[0]), "=r"(r[1]), "=r"(r[2]), "=r"(r[3]) : "r"(addr));
}
__device__ __forceinline__ void mma16816(float* d, const uint32_t* a, const uint32_t* b) {
    asm volatile(
        "mma.sync.aligned.m16n8k16.row.col.f32.bf16.bf16.f32 "
        "{%0,%1,%2,%3}, {%4,%5,%6,%7}, {%8,%9}, {%0,%1,%2,%3};"
        : "+f"(d[0]), "+f"(d[1]), "+f"(d[2]), "+f"(d[3])
        : "r"(a[0]), "r"(a[1]), "r"(a[2]), "r"(a[3]), "r"(b[0]), "r"(b[1]));
}

__device__ __forceinline__ void proj4(float x0, float x1, float x2, float x3,
                                      float& o0, float& o1, float& o2, float& o3) {
    float a0 = fabsf(x0), a1 = fabsf(x1), a2 = fabsf(x2), a3 = fabsf(x3);
    float ssum = a0 + a1 + a2 + a3;
    float m01 = fmaxf(a0, a1), n01 = fminf(a0, a1);
    float m23 = fmaxf(a2, a3), n23 = fminf(a2, a3);
    float s0 = fmaxf(m01, m23), lo0 = fminf(m01, m23);
    float hi1 = fmaxf(n01, n23), s3 = fminf(n01, n23);
    float s1 = fmaxf(lo0, hi1), s2 = fminf(lo0, hi1);
    float c1 = s0 - 1.f, c2 = c1 + s1, c3 = c2 + s2, c4 = c3 + s3;
    int rho = 1 + (s1 * 2.f > c2) + (s2 * 3.f > c3) + (s3 * 4.f > c4);
    float num = (rho == 1) ? c1 : (rho == 2) ? c2 : (rho == 3) ? c3 : c4;
    float theta = fmaxf(num / (float)rho, 0.f);
    theta = (ssum <= 1.f) ? 0.f : theta;
    o0 = copysignf(fmaxf(a0 - theta, 0.f), x0);
    o1 = copysignf(fmaxf(a1 - theta, 0.f), x1);
    o2 = copysignf(fmaxf(a2 - theta, 0.f), x2);
    o3 = copysignf(fmaxf(a3 - theta, 0.f), x3);
}

// ---------------- precompute kernel (unchanged) ----------------
__global__ void precomp_kernel(const float* __restrict__ sigma, const float* __restrict__ Qp,
                               const float* __restrict__ tausp, const float* __restrict__ lambp,
                               const float* __restrict__ epsp,
                               const float* __restrict__ w1, const float* __restrict__ b1,
                               const float* __restrict__ w2, const float* __restrict__ b2,
                               const float* __restrict__ w3, const float* __restrict__ b3) {
    __shared__ float h1[2][F_], h2[2][F_];
    int t = threadIdx.x;
    float lamb_e = expf(lambp[0]);
    float eps_e = expf(epsp[0]);
    if (t == 0) {
        g_pre.eps_e = eps_e;
        g_pre.inv_denom = 1.f / (1.f + lamb_e * (1.f + eps_e));
    }
    if (t < F_) {
        float Qm[4][4];
#pragma unroll
        for (int l = 0; l < 4; l++) {
            float rs = 0.f;
#pragma unroll
            for (int g = 0; g < 4; g++) rs += fabsf(Qp[t * 16 + l * 4 + g]);
            float inv = 1.f / fmaxf(rs, 1.f);
#pragma unroll
            for (int g = 0; g < 4; g++) Qm[l][g] = Qp[t * 16 + l * 4 + g] * inv;
        }
        double S[4][4];
        for (int i = 0; i < 4; i++)
            for (int j = 0; j < 4; j++) {
                double acc = 0.0;
                for (int l = 0; l < 4; l++) acc += (double)Qm[l][i] * (double)Qm[l][j];
                S[i][j] = acc;
            }
        const int JP[6] = {0, 0, 0, 1, 1, 2};
        const int JQ[6] = {1, 2, 3, 2, 3, 3};
        for (int sw = 0; sw < 25; sw++)
            for (int rr = 0; rr < 6; rr++) {
                int p = JP[rr], qq = JQ[rr];
                double apq = S[p][qq];
                if (fabs(apq) < 1e-30) continue;
                double th = (S[qq][qq] - S[p][p]) / (2.0 * apq);
                double tt = (th >= 0.0 ? 1.0 : -1.0) / (fabs(th) + sqrt(1.0 + th * th));
                double cc = 1.0 / sqrt(1.0 + tt * tt), ss = tt * cc;
                for (int k = 0; k < 4; k++) {
                    double skp = S[k][p], skq = S[k][qq];
                    S[k][p] = cc * skp - ss * skq;
                    S[k][qq] = ss * skp + cc * skq;
                }
                for (int k = 0; k < 4; k++) {
                    double spk = S[p][k], sqk = S[qq][k];
                    S[p][k] = cc * spk - ss * sqk;
                    S[qq][k] = ss * spk + cc * sqk;
                }
            }
        double lam = S[0][0];
        for (int i = 1; i < 4; i++) lam = (S[i][i] > lam) ? S[i][i] : lam;
        float inv_lam = (float)(1.0 / lam);
#pragma unroll
        for (int l = 0; l < 4; l++)
#pragma unroll
            for (int g = 0; g < 4; g++) {
                g_pre.Qm[t][l][g] = Qm[l][g];
                g_pre.Qeff[t][l][g] = Qm[l][g] * inv_lam;
            }
        g_pre.its[t] = SCALE_C / expf(fmaxf(tausp[t], 0.f));
        for (int bb = 0; bb < 2; bb++)
            h1[bb][t] = fmaxf(fmaf(sigma[bb] * 20.f - 2.f, w1[t], b1[t]), 0.f);
    }
    __syncthreads();
    if (t < F_)
        for (int bb = 0; bb < 2; bb++) {
            float a = b2[t];
            for (int j = 0; j < F_; j++) a += h1[bb][j] * w2[j * F_ + t];
            h2[bb][t] = fmaxf(a, 0.f);
        }
    __syncthreads();
    if (t < F_)
        for (int bb = 0; bb < 2; bb++) {
            float a = b3[t];
            for (int j = 0; j < F_; j++) a += h2[bb][j] * w3[j * F_ + t];
            float sc = fmaxf(fmaf(a, 0.05f, sigma[bb]), 0.f) + 1e-9f;
            g_pre.invsc[bb][t] = 1.f / sc;
            g_pre.lscal[bb][t] = lamb_e * sc;
        }
}

// ---------------- HMMA main kernel: 3-term fwd, 1-term bwd, spill-free ----------------
__global__ void __launch_bounds__(THREADS, 1)
mfoe_kernel(const float* __restrict__ xn, const float* __restrict__ Wf,
            const int* __restrict__ niter_p, float* __restrict__ out) {
    extern __shared__ char smc[];
    const uint32_t smb = smem_u32(smc);
    const int t = threadIdx.x;
    const int warp = t >> 5, lane = t & 31;
    const int r = lane >> 2, q = lane & 3;
    const int t8 = lane & 7, tb = lane >> 3;

    const int pix0 = blockIdx.x * 128;
    const int b = pix0 >> 14;
    const int sp0 = pix0 & 16383;
    const float* xnw = xn + (size_t)b * (C_ * 16384) + sp0 + warp * 16 + r;
    float* outw = out + (size_t)b * (C_ * 16384) + sp0 + warp * 16 + r;

    // ---- fill weight tiles (scaling folded in) ----
    {
        const float* iscp = g_pre.invsc[b];
        const float* lsp  = g_pre.lscal[b];
        __nv_bfloat16* bfh = (__nv_bfloat16*)(smc + OFF_BFH);
        __nv_bfloat16* bfl = (__nv_bfloat16*)(smc + OFF_BFL);
        __nv_bfloat16* bbh = (__nv_bfloat16*)(smc + OFF_BBH);
        for (int i = t; i < GF * C_; i += THREADS) {
            int e = i >> 7, c = i & 127;
            int f = e % 48;
            float w = Wf[i];
            float wf = w * iscp[f];
            __nv_bfloat16 h = __float2bfloat16(wf);
            bfh[e * BFS + c] = h;
            bfl[e * BFS + c] = __float2bfloat16(wf - __bfloat162float(h));
            bbh[c * BBS + e] = __float2bfloat16(w * lsp[f]);
        }
        float* qes = (float*)(smc + OFF_QE);
        float* qms = (float*)(smc + OFF_QM);
        for (int i = t; i < 768; i += THREADS) {
            qes[i] = ((const float*)g_pre.Qeff)[i] * g_pre.its[i >> 4];
            qms[i] = ((const float*)g_pre.Qm)[i] * SCALE_C;
        }
    }
    __syncthreads();

    const float eps_e = g_pre.eps_e;
    const float inv_denom = g_pre.inv_denom;
    const int niter = *niter_p;
    const float* qes = (const float*)(smc + OFF_QE);
    const float* qms = (const float*)(smc + OFF_QM);

    // ---- x state lives directly as packed bf16 hi/lo A-fragments ----
    uint32_t Ahs[8][4], Als[8][4];
#pragma unroll
    for (int n = 0; n < 16; n++) {
        int c0 = 8 * n + 2 * q;
        float x0 = xnw[(size_t)c0 * 16384];
        float x1 = xnw[(size_t)(c0 + 1) * 16384];
        float x2 = xnw[(size_t)c0 * 16384 + 8];
        float x3 = xnw[(size_t)(c0 + 1) * 16384 + 8];
        int m = n >> 1, base = (n & 1) * 2;
        Ahs[m][base] = packbf(x0, x1);
        float2 h0 = unpackbf(Ahs[m][base]);
        Als[m][base] = packbf(x0 - h0.x, x1 - h0.y);
        Ahs[m][base + 1] = packbf(x2, x3);
        float2 h1 = unpackbf(Ahs[m][base + 1]);
        Als[m][base + 1] = packbf(x2 - h1.x, x3 - h1.y);
    }

    for (int it = 0; it < niter; ++it) {
        // v tiles for the whole iteration, packed bf16 (1-term)
        uint32_t vh[24][2];

        // ===== forward (3-term) + activation, per quad of e-tiles =====
#pragma unroll
        for (int r6 = 0; r6 < 6; r6++) {
            float Df[4][4];
#pragma unroll
            for (int g = 0; g < 4; g++) { Df[g][0] = 0.f; Df[g][1] = 0.f; Df[g][2] = 0.f; Df[g][3] = 0.f; }
#pragma unroll
            for (int jp = 0; jp < 4; jp++) {
                uint32_t rowoff = smb + OFF_BFH + (uint32_t)(t8 * BFS + 32 * jp + 8 * tb) * 2;
#pragma unroll
                for (int g = 0; g < 4; g++) {
                    int n = r6 + 6 * g;
                    uint32_t addr = rowoff + (uint32_t)(8 * n * BFS) * 2;
                    uint32_t bh[4], bl[4];
                    ldsm4(bh, addr);
                    ldsm4(bl, addr + (OFF_BFL - OFF_BFH));
                    mma16816(Df[g], Ahs[2 * jp], bh);
                    mma16816(Df[g], Als[2 * jp], bh);
                    mma16816(Df[g], Ahs[2 * jp], bl);
                    mma16816(Df[g], Ahs[2 * jp + 1], bh + 2);
                    mma16816(Df[g], Als[2 * jp + 1], bh + 2);
                    mma16816(Df[g], Ahs[2 * jp + 1], bl + 2);
                }
            }

            // activation on the quad -> vh[e-tile = r6 + 6g]
            {
                float vt[2][2][4];   // [h][fcol][g]
#pragma unroll
                for (int fcol = 0; fcol < 2; fcol++) {
                    int f = 8 * r6 + 2 * q + fcol;
                    float4 qe0 = *(const float4*)(qes + f * 16);
                    float4 qe1 = *(const float4*)(qes + f * 16 + 4);
                    float4 qe2 = *(const float4*)(qes + f * 16 + 8);
                    float4 qe3 = *(const float4*)(qes + f * 16 + 12);
                    float4 qm0 = *(const float4*)(qms + f * 16);
                    float4 qm1 = *(const float4*)(qms + f * 16 + 4);
                    float4 qm2 = *(const float4*)(qms + f * 16 + 8);
                    float4 qm3 = *(const float4*)(qms + f * 16 + 12);
#pragma unroll
                    for (int h = 0; h < 2; h++) {
                        int di = 2 * h + fcol;
                        float xv0 = Df[0][di], xv1 = Df[1][di];
                        float xv2 = Df[2][di], xv3 = Df[3][di];

                        float gc0, gc1, gc2, gc3;
                        proj4(xv0, xv1, xv2, xv3, gc0, gc1, gc2, gc3);
                        gc0 = fmaf(eps_e, xv0, gc0);
                        gc1 = fmaf(eps_e, xv1, gc1);
                        gc2 = fmaf(eps_e, xv2, gc2);
                        gc3 = fmaf(eps_e, xv3, gc3);

                        float y0 = qe0.x * xv0 + qe0.y * xv1 + qe0.z * xv2 + qe0.w * xv3;
                        float y1 = qe1.x * xv0 + qe1.y * xv1 + qe1.z * xv2 + qe1.w * xv3;
                        float y2 = qe2.x * xv0 + qe2.y * xv1 + qe2.z * xv2 + qe2.w * xv3;
                        float y3 = qe3.x * xv0 + qe3.y * xv1 + qe3.z * xv2 + qe3.w * xv3;

                        float gy0, gy1, gy2, gy3;
                        proj4(y0, y1, y2, y3, gy0, gy1, gy2, gy3);
                        gy0 = fmaf(eps_e, y0, gy0);
                        gy1 = fmaf(eps_e, y1, gy1);
                        gy2 = fmaf(eps_e, y2, gy2);
                        gy3 = fmaf(eps_e, y3, gy3);

                        vt[h][fcol][0] = gc0 - (qm0.x * gy0 + qm1.x * gy1 + qm2.x * gy2 + qm3.x * gy3);
                        vt[h][fcol][1] = gc1 - (qm0.y * gy0 + qm1.y * gy1 + qm2.y * gy2 + qm3.y * gy3);
                        vt[h][fcol][2] = gc2 - (qm0.z * gy0 + qm1.z * gy1 + qm2.z * gy2 + qm3.z * gy3);
                        vt[h][fcol][3] = gc3 - (qm0.w * gy0 + qm1.w * gy1 + qm2.w * gy2 + qm3.w * gy3);
                    }
                }
#pragma unroll
                for (int g = 0; g < 4; g++) {
                    vh[r6 + 6 * g][0] = packbf(vt[0][0][g], vt[0][1][g]);
                    vh[r6 + 6 * g][1] = packbf(vt[1][0][g], vt[1][1][g]);
                }
            }
        }

        // ===== backward (1-term) per c-tile, acc local, immediate x update =====
#pragma unroll
        for (int n = 0; n < 16; n++) {
            float acc[4] = {0.f, 0.f, 0.f, 0.f};
            uint32_t addr0 = smb + OFF_BBH + (uint32_t)((8 * n + t8) * BBS + 8 * tb) * 2;
#pragma unroll
            for (int jp = 0; jp < 6; jp++) {
                uint32_t bh[4];
                ldsm4(bh, addr0 + (uint32_t)(64 * jp));
                uint32_t Ah0[4] = {vh[4 * jp][0], vh[4 * jp][1], vh[4 * jp + 1][0], vh[4 * jp + 1][1]};
                uint32_t Ah1[4] = {vh[4 * jp + 2][0], vh[4 * jp + 2][1], vh[4 * jp + 3][0], vh[4 * jp + 3][1]};
                mma16816(acc, Ah0, bh);
                mma16816(acc, Ah1, bh + 2);
            }
            // x update for this c-tile
            int c0 = 8 * n + 2 * q;
            float n0 = xnw[(size_t)c0 * 16384];
            float n1 = xnw[(size_t)(c0 + 1) * 16384];
            float n2 = xnw[(size_t)c0 * 16384 + 8];
            float n3 = xnw[(size_t)(c0 + 1) * 16384 + 8];
            int m = n >> 1, base = (n & 1) * 2;
            float2 h0 = unpackbf(Ahs[m][base]);
            float2 h1 = unpackbf(Ahs[m][base + 1]);
            float2 l0 = unpackbf(Als[m][base]);
            float2 l1 = unpackbf(Als[m][base + 1]);
            float x0 = h0.x + l0.x, x1 = h0.y + l0.y;
            float x2 = h1.x + l1.x, x3 = h1.y + l1.y;
            x0 -= (x0 - n0 + acc[0]) * inv_denom;
            x1 -= (x1 - n1 + acc[1]) * inv_denom;
            x2 -= (x2 - n2 + acc[2]) * inv_denom;
            x3 -= (x3 - n3 + acc[3]) * inv_denom;
            Ahs[m][base] = packbf(x0, x1);
            float2 nh0 = unpackbf(Ahs[m][base]);
            Als[m][base] = packbf(x0 - nh0.x, x1 - nh0.y);
            Ahs[m][base + 1] = packbf(x2, x3);
            float2 nh1 = unpackbf(Ahs[m][base + 1]);
            Als[m][base + 1] = packbf(x2 - nh1.x, x3 - nh1.y);
        }
    }

    // ---- output: reconstruct and store ----
#pragma unroll
    for (int n = 0; n < 16; n++) {
        int c0 = 8 * n + 2 * q;
        int m = n >> 1, base = (n & 1) * 2;
        float2 h0 = unpackbf(Ahs[m][base]);
        float2 h1 = unpackbf(Ahs[m][base + 1]);
        float2 l0 = unpackbf(Als[m][base]);
        float2 l1 = unpackbf(Als[m][base + 1]);
        outw[(size_t)c0 * 16384] = h0.x + l0.x;
        outw[(size_t)(c0 + 1) * 16384] = h0.y + l0.y;
        outw[(size_t)c0 * 16384 + 8] = h1.x + l1.x;
        outw[(size_t)(c0 + 1) * 16384 + 8] = h1.y + l1.y;
    }
}

extern "C" void kernel_launch(void* const* d_in, const int* in_sizes, int n_in,
                              void* d_out, int out_size) {
    const float* xn    = (const float*)d_in[0];
    const float* sigma = (const float*)d_in[1];
    const float* Qp    = (const float*)d_in[2];
    const float* tausp = (const float*)d_in[3];
    const float* lamb  = (const float*)d_in[4];
    const float* epso  = (const float*)d_in[5];
    const float* w1    = (const float*)d_in[6];
    const float* b1    = (const float*)d_in[7];
    const float* w2    = (const float*)d_in[8];
    const float* b2    = (const float*)d_in[9];
    const float* w3    = (const float*)d_in[10];
    const float* b3    = (const float*)d_in[11];
    const float* Wf    = (const float*)d_in[12];
    const int* niter   = (const int*)d_in[13];
    float* out = (float*)d_out;

    cudaFuncSetAttribute(mfoe_kernel, cudaFuncAttributeMaxDynamicSharedMemorySize, SMEM_BYTES);
    precomp_kernel<<<1, 64>>>(sigma, Qp, tausp, lamb, epso, w1, b1, w2, b2, w3, b3);
    mfoe_kernel<<<256, THREADS, SMEM_BYTES>>>(xn, Wf, niter, out);
}

// round 11
// speedup vs baseline: 3.1213x; 1.0211x over previous
#include <cuda_runtime.h>
#include <cuda_bf16.h>
#include <cstdint>

#define F_ 48
#define C_ 128
#define GF 192
#define THREADS 128
#define SCALE_C 0.999f

// ---- smem layout (bytes) ----
#define BFS 136   // W row stride in bf16 elems (272B -> conflict-free ldmatrix, both trans and non-trans)
#define OFF_W   0                          // W[e][c] bf16, raw (no scaling folded)
#define OFF_QE  (OFF_W + GF*BFS*2)         // 52224
#define OFF_QM  (OFF_QE + 3072)            // 55296
#define OFF_ISC (OFF_QM + 3072)            // 58368
#define OFF_LSC (OFF_ISC + 192)            // 58560
#define SMEM_BYTES (OFF_LSC + 192)         // 58752

struct Precomp {
    float Qeff[F_][4][4];
    float Qm[F_][4][4];
    float its[F_];
    float invsc[2][F_];
    float lscal[2][F_];
    float eps_e;
    float inv_denom;
};
__device__ Precomp g_pre;

__device__ __forceinline__ uint32_t smem_u32(const void* p) {
    uint32_t a;
    asm("{ .reg .u64 t; cvta.to.shared.u64 t, %1; cvt.u32.u64 %0, t; }" : "=r"(a) : "l"(p));
    return a;
}
// pack: a -> low 16 bits, b -> high
__device__ __forceinline__ uint32_t packbf(float a, float b) {
    uint32_t r;
    asm("cvt.rn.bf16x2.f32 %0, %1, %2;" : "=r"(r) : "f"(b), "f"(a));
    return r;
}
__device__ __forceinline__ float2 unpackbf(uint32_t v) {
    float2 r;
    r.x = __uint_as_float(v << 16);
    r.y = __uint_as_float(v & 0xffff0000u);
    return r;
}
__device__ __forceinline__ void ldsm4(uint32_t* r, uint32_t addr) {
    asm volatile("ldmatrix.sync.aligned.m8n8.x4.shared.b16 {%0,%1,%2,%3}, [%4];"
                 : "=r"(r[0]), "=r"(r[1]), "=r"(r[2]), "=r"(r[3]) : "r"(addr));
}
__device__ __forceinline__ void ldsm4t(uint32_t* r, uint32_t addr) {
    asm volatile("ldmatrix.sync.aligned.m8n8.x4.trans.shared.b16 {%0,%1,%2,%3}, [%4];"
                 : "=r"(r[0]), "=r"(r[1]), "=r"(r[2]), "=r"(r[3]) : "r"(addr));
}
__device__ __forceinline__ void mma16816(float* d, const uint32_t* a, const uint32_t* b) {
    asm volatile(
        "mma.sync.aligned.m16n8k16.row.col.f32.bf16.bf16.f32 "
        "{%0,%1,%2,%3}, {%4,%5,%6,%7}, {%8,%9}, {%0,%1,%2,%3};"
        : "+f"(d[0]), "+f"(d[1]), "+f"(d[2]), "+f"(d[3])
        : "r"(a[0]), "r"(a[1]), "r"(a[2]), "r"(a[3]), "r"(b[0]), "r"(b[1]));
}

__device__ __forceinline__ void proj4(float x0, float x1, float x2, float x3,
                                      float& o0, float& o1, float& o2, float& o3) {
    float a0 = fabsf(x0), a1 = fabsf(x1), a2 = fabsf(x2), a3 = fabsf(x3);
    float ssum = a0 + a1 + a2 + a3;
    float m01 = fmaxf(a0, a1), n01 = fminf(a0, a1);
    float m23 = fmaxf(a2, a3), n23 = fminf(a2, a3);
    float s0 = fmaxf(m01, m23), lo0 = fminf(m01, m23);
    float hi1 = fmaxf(n01, n23), s3 = fminf(n01, n23);
    float s1 = fmaxf(lo0, hi1), s2 = fminf(lo0, hi1);
    float c1 = s0 - 1.f, c2 = c1 + s1, c3 = c2 + s2, c4 = c3 + s3;
    int rho = 1 + (s1 * 2.f > c2) + (s2 * 3.f > c3) + (s3 * 4.f > c4);
    float num = (rho == 1) ? c1 : (rho == 2) ? c2 : (rho == 3) ? c3 : c4;
    float theta = fmaxf(num / (float)rho, 0.f);
    theta = (ssum <= 1.f) ? 0.f : theta;
    o0 = copysignf(fmaxf(a0 - theta, 0.f), x0);
    o1 = copysignf(fmaxf(a1 - theta, 0.f), x1);
    o2 = copysignf(fmaxf(a2 - theta, 0.f), x2);
    o3 = copysignf(fmaxf(a3 - theta, 0.f), x3);
}

// ---------------- precompute kernel (float Jacobi, 12 sweeps) ----------------
__global__ void precomp_kernel(const float* __restrict__ sigma, const float* __restrict__ Qp,
                               const float* __restrict__ tausp, const float* __restrict__ lambp,
                               const float* __restrict__ epsp,
                               const float* __restrict__ w1, const float* __restrict__ b1,
                               const float* __restrict__ w2, const float* __restrict__ b2,
                               const float* __restrict__ w3, const float* __restrict__ b3) {
    __shared__ float h1[2][F_], h2[2][F_];
    int t = threadIdx.x;
    float lamb_e = expf(lambp[0]);
    float eps_e = expf(epsp[0]);
    if (t == 0) {
        g_pre.eps_e = eps_e;
        g_pre.inv_denom = 1.f / (1.f + lamb_e * (1.f + eps_e));
    }
    if (t < F_) {
        float Qm[4][4];
#pragma unroll
        for (int l = 0; l < 4; l++) {
            float rs = 0.f;
#pragma unroll
            for (int g = 0; g < 4; g++) rs += fabsf(Qp[t * 16 + l * 4 + g]);
            float inv = 1.f / fmaxf(rs, 1.f);
#pragma unroll
            for (int g = 0; g < 4; g++) Qm[l][g] = Qp[t * 16 + l * 4 + g] * inv;
        }
        float S[4][4];
        for (int i = 0; i < 4; i++)
            for (int j = 0; j < 4; j++) {
                float acc = 0.f;
                for (int l = 0; l < 4; l++) acc += Qm[l][i] * Qm[l][j];
                S[i][j] = acc;
            }
        const int JP[6] = {0, 0, 0, 1, 1, 2};
        const int JQ[6] = {1, 2, 3, 2, 3, 3};
        for (int sw = 0; sw < 12; sw++)
            for (int rr = 0; rr < 6; rr++) {
                int p = JP[rr], qq = JQ[rr];
                float apq = S[p][qq];
                if (fabsf(apq) < 1e-20f) continue;
                float th = (S[qq][qq] - S[p][p]) / (2.f * apq);
                float tt = (th >= 0.f ? 1.f : -1.f) / (fabsf(th) + sqrtf(1.f + th * th));
                float cc = rsqrtf(1.f + tt * tt), ss = tt * cc;
                for (int k = 0; k < 4; k++) {
                    float skp = S[k][p], skq = S[k][qq];
                    S[k][p] = cc * skp - ss * skq;
                    S[k][qq] = ss * skp + cc * skq;
                }
                for (int k = 0; k < 4; k++) {
                    float spk = S[p][k], sqk = S[qq][k];
                    S[p][k] = cc * spk - ss * sqk;
                    S[qq][k] = ss * spk + cc * sqk;
                }
            }
        float lam = S[0][0];
        for (int i = 1; i < 4; i++) lam = (S[i][i] > lam) ? S[i][i] : lam;
        float inv_lam = 1.f / lam;
#pragma unroll
        for (int l = 0; l < 4; l++)
#pragma unroll
            for (int g = 0; g < 4; g++) {
                g_pre.Qm[t][l][g] = Qm[l][g];
                g_pre.Qeff[t][l][g] = Qm[l][g] * inv_lam;
            }
        g_pre.its[t] = SCALE_C / expf(fmaxf(tausp[t], 0.f));
        for (int bb = 0; bb < 2; bb++)
            h1[bb][t] = fmaxf(fmaf(sigma[bb] * 20.f - 2.f, w1[t], b1[t]), 0.f);
    }
    __syncthreads();
    if (t < F_)
        for (int bb = 0; bb < 2; bb++) {
            float a = b2[t];
            for (int j = 0; j < F_; j++) a += h1[bb][j] * w2[j * F_ + t];
            h2[bb][t] = fmaxf(a, 0.f);
        }
    __syncthreads();
    if (t < F_)
        for (int bb = 0; bb < 2; bb++) {
            float a = b3[t];
            for (int j = 0; j < F_; j++) a += h2[bb][j] * w3[j * F_ + t];
            float sc = fmaxf(fmaf(a, 0.05f, sigma[bb]), 0.f) + 1e-9f;
            g_pre.invsc[bb][t] = 1.f / sc;
            g_pre.lscal[bb][t] = lamb_e * sc;
        }
}

// ---------------- HMMA main kernel: 128 thr / 3 CTAs per SM, shared W tile ----------------
__global__ void __launch_bounds__(THREADS, 3)
mfoe_kernel(const float* __restrict__ xn, const float* __restrict__ Wf,
            const int* __restrict__ niter_p, float* __restrict__ out) {
    extern __shared__ char smc[];
    const uint32_t smb = smem_u32(smc);
    const int t = threadIdx.x;
    const int warp = t >> 5, lane = t & 31;
    const int r = lane >> 2, q = lane & 3;
    const int t8 = lane & 7, tb = lane >> 3;

    const int pix0 = blockIdx.x * 64;
    const int b = pix0 >> 14;
    const int sp0 = pix0 & 16383;
    const float* xnw = xn + (size_t)b * (C_ * 16384) + sp0 + warp * 16 + r;
    float* outw = out + (size_t)b * (C_ * 16384) + sp0 + warp * 16 + r;

    // ---- fill shared W tile (raw bf16) + Q tables + per-f scalars ----
    {
        __nv_bfloat16* wt = (__nv_bfloat16*)(smc + OFF_W);
        for (int i = t; i < GF * C_; i += THREADS) {
            int e = i >> 7, c = i & 127;
            wt[e * BFS + c] = __float2bfloat16(Wf[i]);
        }
        float* qes = (float*)(smc + OFF_QE);
        float* qms = (float*)(smc + OFF_QM);
        for (int i = t; i < 768; i += THREADS) {
            qes[i] = ((const float*)g_pre.Qeff)[i] * g_pre.its[i >> 4];
            qms[i] = ((const float*)g_pre.Qm)[i] * SCALE_C;
        }
        if (t < F_) {
            ((float*)(smc + OFF_ISC))[t] = g_pre.invsc[b][t];
            ((float*)(smc + OFF_LSC))[t] = g_pre.lscal[b][t];
        }
    }
    __syncthreads();

    const float eps_e = g_pre.eps_e;
    const float inv_denom = g_pre.inv_denom;
    const int niter = *niter_p;
    const float* qes = (const float*)(smc + OFF_QE);
    const float* qms = (const float*)(smc + OFF_QM);
    const float* ISC = (const float*)(smc + OFF_ISC);
    const float* LSC = (const float*)(smc + OFF_LSC);

    // ---- x state as packed bf16 hi/lo A-fragments ----
    uint32_t Ahs[8][4], Als[8][4];
#pragma unroll
    for (int n = 0; n < 16; n++) {
        int c0 = 8 * n + 2 * q;
        float x0 = xnw[(size_t)c0 * 16384];
        float x1 = xnw[(size_t)(c0 + 1) * 16384];
        float x2 = xnw[(size_t)c0 * 16384 + 8];
        float x3 = xnw[(size_t)(c0 + 1) * 16384 + 8];
        int m = n >> 1, base = (n & 1) * 2;
        Ahs[m][base] = packbf(x0, x1);
        float2 h0 = unpackbf(Ahs[m][base]);
        Als[m][base] = packbf(x0 - h0.x, x1 - h0.y);
        Ahs[m][base + 1] = packbf(x2, x3);
        float2 h1 = unpackbf(Ahs[m][base + 1]);
        Als[m][base + 1] = packbf(x2 - h1.x, x3 - h1.y);
    }

    for (int it = 0; it < niter; ++it) {
        uint32_t vh[24][2];   // v tiles, packed bf16

        // ===== forward (2-term: exact x, bf16 W) + activation =====
#pragma unroll
        for (int r6 = 0; r6 < 6; r6++) {
            float Df[4][4];
#pragma unroll
            for (int g = 0; g < 4; g++) { Df[g][0] = 0.f; Df[g][1] = 0.f; Df[g][2] = 0.f; Df[g][3] = 0.f; }
#pragma unroll
            for (int jp = 0; jp < 4; jp++) {
                uint32_t rowoff = smb + OFF_W + (uint32_t)(t8 * BFS + 32 * jp + 8 * tb) * 2;
#pragma unroll
                for (int g = 0; g < 4; g++) {
                    int n = r6 + 6 * g;
                    uint32_t bh[4];
                    ldsm4(bh, rowoff + (uint32_t)(8 * n * BFS) * 2);
                    mma16816(Df[g], Ahs[2 * jp], bh);
                    mma16816(Df[g], Als[2 * jp], bh);
                    mma16816(Df[g], Ahs[2 * jp + 1], bh + 2);
                    mma16816(Df[g], Als[2 * jp + 1], bh + 2);
                }
            }

            // activation on the quad -> vh[e-tile = r6 + 6g]
            {
                float vt[2][2][4];   // [h][fcol][g]
#pragma unroll
                for (int fcol = 0; fcol < 2; fcol++) {
                    int f = 8 * r6 + 2 * q + fcol;
                    float isc = ISC[f];
                    float ls  = LSC[f];
                    float4 qe0 = *(const float4*)(qes + f * 16);
                    float4 qe1 = *(const float4*)(qes + f * 16 + 4);
                    float4 qe2 = *(const float4*)(qes + f * 16 + 8);
                    float4 qe3 = *(const float4*)(qes + f * 16 + 12);
                    float4 qm0 = *(const float4*)(qms + f * 16);
                    float4 qm1 = *(const float4*)(qms + f * 16 + 4);
                    float4 qm2 = *(const float4*)(qms + f * 16 + 8);
                    float4 qm3 = *(const float4*)(qms + f * 16 + 12);
#pragma unroll
                    for (int h = 0; h < 2; h++) {
                        int di = 2 * h + fcol;
                        float xv0 = Df[0][di] * isc, xv1 = Df[1][di] * isc;
                        float xv2 = Df[2][di] * isc, xv3 = Df[3][di] * isc;

                        float gc0, gc1, gc2, gc3;
                        proj4(xv0, xv1, xv2, xv3, gc0, gc1, gc2, gc3);
                        gc0 = fmaf(eps_e, xv0, gc0);
                        gc1 = fmaf(eps_e, xv1, gc1);
                        gc2 = fmaf(eps_e, xv2, gc2);
                        gc3 = fmaf(eps_e, xv3, gc3);

                        float y0 = qe0.x * xv0 + qe0.y * xv1 + qe0.z * xv2 + qe0.w * xv3;
                        float y1 = qe1.x * xv0 + qe1.y * xv1 + qe1.z * xv2 + qe1.w * xv3;
                        float y2 = qe2.x * xv0 + qe2.y * xv1 + qe2.z * xv2 + qe2.w * xv3;
                        float y3 = qe3.x * xv0 + qe3.y * xv1 + qe3.z * xv2 + qe3.w * xv3;

                        float gy0, gy1, gy2, gy3;
                        proj4(y0, y1, y2, y3, gy0, gy1, gy2, gy3);
                        gy0 = fmaf(eps_e, y0, gy0);
                        gy1 = fmaf(eps_e, y1, gy1);
                        gy2 = fmaf(eps_e, y2, gy2);
                        gy3 = fmaf(eps_e, y3, gy3);

                        vt[h][fcol][0] = ls * (gc0 - (qm0.x * gy0 + qm1.x * gy1 + qm2.x * gy2 + qm3.x * gy3));
                        vt[h][fcol][1] = ls * (gc1 - (qm0.y * gy0 + qm1.y * gy1 + qm2.y * gy2 + qm3.y * gy3));
                        vt[h][fcol][2] = ls * (gc2 - (qm0.z * gy0 + qm1.z * gy1 + qm2.z * gy2 + qm3.z * gy3));
                        vt[h][fcol][3] = ls * (gc3 - (qm0.w * gy0 + qm1.w * gy1 + qm2.w * gy2 + qm3.w * gy3));
                    }
                }
#pragma unroll
                for (int g = 0; g < 4; g++) {
                    vh[r6 + 6 * g][0] = packbf(vt[0][0][g], vt[0][1][g]);
                    vh[r6 + 6 * g][1] = packbf(vt[1][0][g], vt[1][1][g]);
                }
            }
        }

        // ===== backward (1-term, trans-ldsm from the SAME W tile) + x update =====
#pragma unroll
        for (int p = 0; p < 8; p++) {
            float acc0[4] = {0.f, 0.f, 0.f, 0.f};
            float acc1[4] = {0.f, 0.f, 0.f, 0.f};
            uint32_t coloff = (uint32_t)(16 * p + 8 * (tb >> 1)) * 2;
            uint32_t rowb = (uint32_t)(t8 + 8 * (tb & 1));
#pragma unroll
            for (int jp = 0; jp < 12; jp++) {
                uint32_t bt[4];
                ldsm4t(bt, smb + OFF_W + (uint32_t)((16 * jp + rowb) * BFS) * 2 + coloff);
                uint32_t A[4] = {vh[2 * jp][0], vh[2 * jp][1], vh[2 * jp + 1][0], vh[2 * jp + 1][1]};
                mma16816(acc0, A, bt);
                mma16816(acc1, A, bt + 2);
            }
#pragma unroll
            for (int s = 0; s < 2; s++) {
                const float* ac = s ? acc1 : acc0;
                int n = 2 * p + s;
                int c0 = 8 * n + 2 * q;
                float n0 = xnw[(size_t)c0 * 16384];
                float n1 = xnw[(size_t)(c0 + 1) * 16384];
                float n2 = xnw[(size_t)c0 * 16384 + 8];
                float n3 = xnw[(size_t)(c0 + 1) * 16384 + 8];
                int m = p, base = s * 2;
                float2 h0 = unpackbf(Ahs[m][base]);
                float2 h1 = unpackbf(Ahs[m][base + 1]);
                float2 l0 = unpackbf(Als[m][base]);
                float2 l1 = unpackbf(Als[m][base + 1]);
                float x0 = h0.x + l0.x, x1 = h0.y + l0.y;
                float x2 = h1.x + l1.x, x3 = h1.y + l1.y;
                x0 -= (x0 - n0 + ac[0]) * inv_denom;
                x1 -= (x1 - n1 + ac[1]) * inv_denom;
                x2 -= (x2 - n2 + ac[2]) * inv_denom;
                x3 -= (x3 - n3 + ac[3]) * inv_denom;
                Ahs[m][base] = packbf(x0, x1);
                float2 nh0 = unpackbf(Ahs[m][base]);
                Als[m][base] = packbf(x0 - nh0.x, x1 - nh0.y);
                Ahs[m][base + 1] = packbf(x2, x3);
                float2 nh1 = unpackbf(Ahs[m][base + 1]);
                Als[m][base + 1] = packbf(x2 - nh1.x, x3 - nh1.y);
            }
        }
    }

    // ---- output: reconstruct and store ----
#pragma unroll
    for (int n = 0; n < 16; n++) {
        int c0 = 8 * n + 2 * q;
        int m = n >> 1, base = (n & 1) * 2;
        float2 h0 = unpackbf(Ahs[m][base]);
        float2 h1 = unpackbf(Ahs[m][base + 1]);
        float2 l0 = unpackbf(Als[m][base]);
        float2 l1 = unpackbf(Als[m][base + 1]);
        outw[(size_t)c0 * 16384] = h0.x + l0.x;
        outw[(size_t)(c0 + 1) * 16384] = h0.y + l0.y;
        outw[(size_t)c0 * 16384 + 8] = h1.x + l1.x;
        outw[(size_t)(c0 + 1) * 16384 + 8] = h1.y + l1.y;
    }
}

extern "C" void kernel_launch(void* const* d_in, const int* in_sizes, int n_in,
                              void* d_out, int out_size) {
    const float* xn    = (const float*)d_in[0];
    const float* sigma = (const float*)d_in[1];
    const float* Qp    = (const float*)d_in[2];
    const float* tausp = (const float*)d_in[3];
    const float* lamb  = (const float*)d_in[4];
    const float* epso  = (const float*)d_in[5];
    const float* w1    = (const float*)d_in[6];
    const float* b1    = (const float*)d_in[7];
    const float* w2    = (const float*)d_in[8];
    const float* b2    = (const float*)d_in[9];
    const float* w3    = (const float*)d_in[10];
    const float* b3    = (const float*)d_in[11];
    const float* Wf    = (const float*)d_in[12];
    const int* niter   = (const int*)d_in[13];
    float* out = (float*)d_out;

    cudaFuncSetAttribute(mfoe_kernel, cudaFuncAttributeMaxDynamicSharedMemorySize, SMEM_BYTES);
    precomp_kernel<<<1, 64>>>(sigma, Qp, tausp, lamb, epso, w1, b1, w2, b2, w3, b3);
    mfoe_kernel<<<512, THREADS, SMEM_BYTES>>>(xn, Wf, niter, out);
}

// round 12
// speedup vs baseline: 3.9367x; 1.2612x over previous
#include <cuda_runtime.h>
#include <cuda_bf16.h>
#include <cstdint>

#define F_ 48
#define C_ 128
#define GF 192
#define THREADS 128
#define SCALE_C 0.999f

// ---- smem layout (bytes) ----
#define BFS 136   // W row stride in bf16 elems (272B -> conflict-free ldmatrix, trans and non-trans)
#define OFF_W   0                          // W[e][c] bf16, raw
#define OFF_QE  (OFF_W + GF*BFS*2)         // 52224
#define OFF_QM  (OFF_QE + 3072)            // 55296
#define OFF_ISC (OFF_QM + 3072)            // 58368
#define OFF_LSC (OFF_ISC + 192)            // 58560
#define SMEM_BYTES (OFF_LSC + 192)         // 58752

struct Precomp {
    float Qeff[F_][4][4];
    float Qm[F_][4][4];
    float its[F_];
    float invsc[2][F_];
    float lscal[2][F_];
    float eps_e;
    float inv_denom;
};
__device__ Precomp g_pre;

__device__ __forceinline__ uint32_t smem_u32(const void* p) {
    uint32_t a;
    asm("{ .reg .u64 t; cvta.to.shared.u64 t, %1; cvt.u32.u64 %0, t; }" : "=r"(a) : "l"(p));
    return a;
}
// pack: a -> low 16 bits, b -> high
__device__ __forceinline__ uint32_t packbf(float a, float b) {
    uint32_t r;
    asm("cvt.rn.bf16x2.f32 %0, %1, %2;" : "=r"(r) : "f"(b), "f"(a));
    return r;
}
__device__ __forceinline__ float2 unpackbf(uint32_t v) {
    float2 r;
    r.x = __uint_as_float(v << 16);
    r.y = __uint_as_float(v & 0xffff0000u);
    return r;
}
__device__ __forceinline__ void ldsm4(uint32_t* r, uint32_t addr) {
    asm volatile("ldmatrix.sync.aligned.m8n8.x4.shared.b16 {%0,%1,%2,%3}, [%4];"
                 : "=r"(r[0]), "=r"(r[1]), "=r"(r[2]), "=r"(r[3]) : "r"(addr));
}
__device__ __forceinline__ void ldsm4t(uint32_t* r, uint32_t addr) {
    asm volatile("ldmatrix.sync.aligned.m8n8.x4.trans.shared.b16 {%0,%1,%2,%3}, [%4];"
                 : "=r"(r[0]), "=r"(r[1]), "=r"(r[2]), "=r"(r[3]) : "r"(addr));
}
__device__ __forceinline__ void mma16816(float* d, const uint32_t* a, const uint32_t* b) {
    asm volatile(
        "mma.sync.aligned.m16n8k16.row.col.f32.bf16.bf16.f32 "
        "{%0,%1,%2,%3}, {%4,%5,%6,%7}, {%8,%9}, {%0,%1,%2,%3};"
        : "+f"(d[0]), "+f"(d[1]), "+f"(d[2]), "+f"(d[3])
        : "r"(a[0]), "r"(a[1]), "r"(a[2]), "r"(a[3]), "r"(b[0]), "r"(b[1]));
}

__device__ __forceinline__ void proj4(float x0, float x1, float x2, float x3,
                                      float& o0, float& o1, float& o2, float& o3) {
    float a0 = fabsf(x0), a1 = fabsf(x1), a2 = fabsf(x2), a3 = fabsf(x3);
    float ssum = a0 + a1 + a2 + a3;
    float m01 = fmaxf(a0, a1), n01 = fminf(a0, a1);
    float m23 = fmaxf(a2, a3), n23 = fminf(a2, a3);
    float s0 = fmaxf(m01, m23), lo0 = fminf(m01, m23);
    float hi1 = fmaxf(n01, n23), s3 = fminf(n01, n23);
    float s1 = fmaxf(lo0, hi1), s2 = fminf(lo0, hi1);
    float c1 = s0 - 1.f, c2 = c1 + s1, c3 = c2 + s2, c4 = c3 + s3;
    int rho = 1 + (s1 * 2.f > c2) + (s2 * 3.f > c3) + (s3 * 4.f > c4);
    float num = (rho == 1) ? c1 : (rho == 2) ? c2 : (rho == 3) ? c3 : c4;
    float theta = fmaxf(num / (float)rho, 0.f);
    theta = (ssum <= 1.f) ? 0.f : theta;
    o0 = copysignf(fmaxf(a0 - theta, 0.f), x0);
    o1 = copysignf(fmaxf(a1 - theta, 0.f), x1);
    o2 = copysignf(fmaxf(a2 - theta, 0.f), x2);
    o3 = copysignf(fmaxf(a3 - theta, 0.f), x3);
}

// ---------------- precompute kernel (float Jacobi, 12 sweeps) ----------------
__global__ void precomp_kernel(const float* __restrict__ sigma, const float* __restrict__ Qp,
                               const float* __restrict__ tausp, const float* __restrict__ lambp,
                               const float* __restrict__ epsp,
                               const float* __restrict__ w1, const float* __restrict__ b1,
                               const float* __restrict__ w2, const float* __restrict__ b2,
                               const float* __restrict__ w3, const float* __restrict__ b3) {
    __shared__ float h1[2][F_], h2[2][F_];
    int t = threadIdx.x;
    float lamb_e = expf(lambp[0]);
    float eps_e = expf(epsp[0]);
    if (t == 0) {
        g_pre.eps_e = eps_e;
        g_pre.inv_denom = 1.f / (1.f + lamb_e * (1.f + eps_e));
    }
    if (t < F_) {
        float Qm[4][4];
#pragma unroll
        for (int l = 0; l < 4; l++) {
            float rs = 0.f;
#pragma unroll
            for (int g = 0; g < 4; g++) rs += fabsf(Qp[t * 16 + l * 4 + g]);
            float inv = 1.f / fmaxf(rs, 1.f);
#pragma unroll
            for (int g = 0; g < 4; g++) Qm[l][g] = Qp[t * 16 + l * 4 + g] * inv;
        }
        float S[4][4];
        for (int i = 0; i < 4; i++)
            for (int j = 0; j < 4; j++) {
                float acc = 0.f;
                for (int l = 0; l < 4; l++) acc += Qm[l][i] * Qm[l][j];
                S[i][j] = acc;
            }
        const int JP[6] = {0, 0, 0, 1, 1, 2};
        const int JQ[6] = {1, 2, 3, 2, 3, 3};
        for (int sw = 0; sw < 12; sw++)
            for (int rr = 0; rr < 6; rr++) {
                int p = JP[rr], qq = JQ[rr];
                float apq = S[p][qq];
                if (fabsf(apq) < 1e-20f) continue;
                float th = (S[qq][qq] - S[p][p]) / (2.f * apq);
                float tt = (th >= 0.f ? 1.f : -1.f) / (fabsf(th) + sqrtf(1.f + th * th));
                float cc = rsqrtf(1.f + tt * tt), ss = tt * cc;
                for (int k = 0; k < 4; k++) {
                    float skp = S[k][p], skq = S[k][qq];
                    S[k][p] = cc * skp - ss * skq;
                    S[k][qq] = ss * skp + cc * skq;
                }
                for (int k = 0; k < 4; k++) {
                    float spk = S[p][k], sqk = S[qq][k];
                    S[p][k] = cc * spk - ss * sqk;
                    S[qq][k] = ss * spk + cc * sqk;
                }
            }
        float lam = S[0][0];
        for (int i = 1; i < 4; i++) lam = (S[i][i] > lam) ? S[i][i] : lam;
        float inv_lam = 1.f / lam;
#pragma unroll
        for (int l = 0; l < 4; l++)
#pragma unroll
            for (int g = 0; g < 4; g++) {
                g_pre.Qm[t][l][g] = Qm[l][g];
                g_pre.Qeff[t][l][g] = Qm[l][g] * inv_lam;
            }
        g_pre.its[t] = SCALE_C / expf(fmaxf(tausp[t], 0.f));
        for (int bb = 0; bb < 2; bb++)
            h1[bb][t] = fmaxf(fmaf(sigma[bb] * 20.f - 2.f, w1[t], b1[t]), 0.f);
    }
    __syncthreads();
    if (t < F_)
        for (int bb = 0; bb < 2; bb++) {
            float a = b2[t];
            for (int j = 0; j < F_; j++) a += h1[bb][j] * w2[j * F_ + t];
            h2[bb][t] = fmaxf(a, 0.f);
        }
    __syncthreads();
    if (t < F_)
        for (int bb = 0; bb < 2; bb++) {
            float a = b3[t];
            for (int j = 0; j < F_; j++) a += h2[bb][j] * w3[j * F_ + t];
            float sc = fmaxf(fmaf(a, 0.05f, sigma[bb]), 0.f) + 1e-9f;
            g_pre.invsc[bb][t] = 1.f / sc;
            g_pre.lscal[bb][t] = lamb_e * sc;
        }
}

// ---------------- HMMA main kernel: 128 thr, 2 CTAs/SM, spill-free ----------------
__global__ void __launch_bounds__(THREADS, 2)
mfoe_kernel(const float* __restrict__ xn, const float* __restrict__ Wf,
            const int* __restrict__ niter_p, float* __restrict__ out) {
    extern __shared__ char smc[];
    const uint32_t smb = smem_u32(smc);
    const int t = threadIdx.x;
    const int warp = t >> 5, lane = t & 31;
    const int r = lane >> 2, q = lane & 3;
    const int t8 = lane & 7, tb = lane >> 3;

    const int pix0 = blockIdx.x * 64;
    const int b = pix0 >> 14;
    const int sp0 = pix0 & 16383;
    const float* xnw = xn + (size_t)b * (C_ * 16384) + sp0 + warp * 16 + r;
    float* outw = out + (size_t)b * (C_ * 16384) + sp0 + warp * 16 + r;

    // ---- fill shared W tile (raw bf16) + Q tables + per-f scalars ----
    {
        __nv_bfloat16* wt = (__nv_bfloat16*)(smc + OFF_W);
        for (int i = t; i < GF * C_; i += THREADS) {
            int e = i >> 7, c = i & 127;
            wt[e * BFS + c] = __float2bfloat16(Wf[i]);
        }
        float* qes = (float*)(smc + OFF_QE);
        float* qms = (float*)(smc + OFF_QM);
        for (int i = t; i < 768; i += THREADS) {
            qes[i] = ((const float*)g_pre.Qeff)[i] * g_pre.its[i >> 4];
            qms[i] = ((const float*)g_pre.Qm)[i] * SCALE_C;
        }
        if (t < F_) {
            ((float*)(smc + OFF_ISC))[t] = g_pre.invsc[b][t];
            ((float*)(smc + OFF_LSC))[t] = g_pre.lscal[b][t];
        }
    }
    __syncthreads();

    const float eps_e = g_pre.eps_e;
    const float inv_denom = g_pre.inv_denom;
    const int niter = *niter_p;
    const float* qes = (const float*)(smc + OFF_QE);
    const float* qms = (const float*)(smc + OFF_QM);
    const float* ISC = (const float*)(smc + OFF_ISC);
    const float* LSC = (const float*)(smc + OFF_LSC);

    // ---- x state as packed bf16 hi/lo A-fragments ----
    uint32_t Ahs[8][4], Als[8][4];
#pragma unroll
    for (int n = 0; n < 16; n++) {
        int c0 = 8 * n + 2 * q;
        float x0 = xnw[(size_t)c0 * 16384];
        float x1 = xnw[(size_t)(c0 + 1) * 16384];
        float x2 = xnw[(size_t)c0 * 16384 + 8];
        float x3 = xnw[(size_t)(c0 + 1) * 16384 + 8];
        int m = n >> 1, base = (n & 1) * 2;
        Ahs[m][base] = packbf(x0, x1);
        float2 h0 = unpackbf(Ahs[m][base]);
        Als[m][base] = packbf(x0 - h0.x, x1 - h0.y);
        Ahs[m][base + 1] = packbf(x2, x3);
        float2 h1 = unpackbf(Ahs[m][base + 1]);
        Als[m][base + 1] = packbf(x2 - h1.x, x3 - h1.y);
    }

    for (int it = 0; it < niter; ++it) {
        uint32_t vh[24][2];   // v tiles, packed bf16

        // ===== forward (2-term: exact x, bf16 W) + activation =====
#pragma unroll
        for (int r6 = 0; r6 < 6; r6++) {
            float Df[4][4];
#pragma unroll
            for (int g = 0; g < 4; g++) { Df[g][0] = 0.f; Df[g][1] = 0.f; Df[g][2] = 0.f; Df[g][3] = 0.f; }
#pragma unroll
            for (int jp = 0; jp < 4; jp++) {
                uint32_t rowoff = smb + OFF_W + (uint32_t)(t8 * BFS + 32 * jp + 8 * tb) * 2;
#pragma unroll
                for (int g = 0; g < 4; g++) {
                    int n = r6 + 6 * g;
                    uint32_t bh[4];
                    ldsm4(bh, rowoff + (uint32_t)(8 * n * BFS) * 2);
                    mma16816(Df[g], Ahs[2 * jp], bh);
                    mma16816(Df[g], Als[2 * jp], bh);
                    mma16816(Df[g], Ahs[2 * jp + 1], bh + 2);
                    mma16816(Df[g], Als[2 * jp + 1], bh + 2);
                }
            }

            // activation on the quad -> vh[e-tile = r6 + 6g]
            {
                float vt[2][2][4];   // [h][fcol][g]
#pragma unroll
                for (int fcol = 0; fcol < 2; fcol++) {
                    int f = 8 * r6 + 2 * q + fcol;
                    float isc = ISC[f];
                    float ls  = LSC[f];
                    float4 qe0 = *(const float4*)(qes + f * 16);
                    float4 qe1 = *(const float4*)(qes + f * 16 + 4);
                    float4 qe2 = *(const float4*)(qes + f * 16 + 8);
                    float4 qe3 = *(const float4*)(qes + f * 16 + 12);
                    float4 qm0 = *(const float4*)(qms + f * 16);
                    float4 qm1 = *(const float4*)(qms + f * 16 + 4);
                    float4 qm2 = *(const float4*)(qms + f * 16 + 8);
                    float4 qm3 = *(const float4*)(qms + f * 16 + 12);
#pragma unroll
                    for (int h = 0; h < 2; h++) {
                        int di = 2 * h + fcol;
                        float xv0 = Df[0][di] * isc, xv1 = Df[1][di] * isc;
                        float xv2 = Df[2][di] * isc, xv3 = Df[3][di] * isc;

                        float gc0, gc1, gc2, gc3;
                        proj4(xv0, xv1, xv2, xv3, gc0, gc1, gc2, gc3);
                        gc0 = fmaf(eps_e, xv0, gc0);
                        gc1 = fmaf(eps_e, xv1, gc1);
                        gc2 = fmaf(eps_e, xv2, gc2);
                        gc3 = fmaf(eps_e, xv3, gc3);

                        float y0 = qe0.x * xv0 + qe0.y * xv1 + qe0.z * xv2 + qe0.w * xv3;
                        float y1 = qe1.x * xv0 + qe1.y * xv1 + qe1.z * xv2 + qe1.w * xv3;
                        float y2 = qe2.x * xv0 + qe2.y * xv1 + qe2.z * xv2 + qe2.w * xv3;
                        float y3 = qe3.x * xv0 + qe3.y * xv1 + qe3.z * xv2 + qe3.w * xv3;

                        float gy0, gy1, gy2, gy3;
                        proj4(y0, y1, y2, y3, gy0, gy1, gy2, gy3);
                        gy0 = fmaf(eps_e, y0, gy0);
                        gy1 = fmaf(eps_e, y1, gy1);
                        gy2 = fmaf(eps_e, y2, gy2);
                        gy3 = fmaf(eps_e, y3, gy3);

                        vt[h][fcol][0] = ls * (gc0 - (qm0.x * gy0 + qm1.x * gy1 + qm2.x * gy2 + qm3.x * gy3));
                        vt[h][fcol][1] = ls * (gc1 - (qm0.y * gy0 + qm1.y * gy1 + qm2.y * gy2 + qm3.y * gy3));
                        vt[h][fcol][2] = ls * (gc2 - (qm0.z * gy0 + qm1.z * gy1 + qm2.z * gy2 + qm3.z * gy3));
                        vt[h][fcol][3] = ls * (gc3 - (qm0.w * gy0 + qm1.w * gy1 + qm2.w * gy2 + qm3.w * gy3));
                    }
                }
#pragma unroll
                for (int g = 0; g < 4; g++) {
                    vh[r6 + 6 * g][0] = packbf(vt[0][0][g], vt[0][1][g]);
                    vh[r6 + 6 * g][1] = packbf(vt[1][0][g], vt[1][1][g]);
                }
            }
        }

        // ===== backward (1-term, trans-ldsm from the SAME W tile) + x update =====
#pragma unroll
        for (int p = 0; p < 8; p++) {
            float acc0[4] = {0.f, 0.f, 0.f, 0.f};
            float acc1[4] = {0.f, 0.f, 0.f, 0.f};
            uint32_t coloff = (uint32_t)(16 * p + 8 * (tb >> 1)) * 2;
            uint32_t rowb = (uint32_t)(t8 + 8 * (tb & 1));
#pragma unroll
            for (int jp = 0; jp < 12; jp++) {
                uint32_t bt[4];
                ldsm4t(bt, smb + OFF_W + (uint32_t)((16 * jp + rowb) * BFS) * 2 + coloff);
                uint32_t A[4] = {vh[2 * jp][0], vh[2 * jp][1], vh[2 * jp + 1][0], vh[2 * jp + 1][1]};
                mma16816(acc0, A, bt);
                mma16816(acc1, A, bt + 2);
            }
#pragma unroll
            for (int s = 0; s < 2; s++) {
                const float* ac = s ? acc1 : acc0;
                int n = 2 * p + s;
                int c0 = 8 * n + 2 * q;
                float n0 = xnw[(size_t)c0 * 16384];
                float n1 = xnw[(size_t)(c0 + 1) * 16384];
                float n2 = xnw[(size_t)c0 * 16384 + 8];
                float n3 = xnw[(size_t)(c0 + 1) * 16384 + 8];
                int m = p, base = s * 2;
                float2 h0 = unpackbf(Ahs[m][base]);
                float2 h1 = unpackbf(Ahs[m][base + 1]);
                float2 l0 = unpackbf(Als[m][base]);
                float2 l1 = unpackbf(Als[m][base + 1]);
                float x0 = h0.x + l0.x, x1 = h0.y + l0.y;
                float x2 = h1.x + l1.x, x3 = h1.y + l1.y;
                x0 -= (x0 - n0 + ac[0]) * inv_denom;
                x1 -= (x1 - n1 + ac[1]) * inv_denom;
                x2 -= (x2 - n2 + ac[2]) * inv_denom;
                x3 -= (x3 - n3 + ac[3]) * inv_denom;
                Ahs[m][base] = packbf(x0, x1);
                float2 nh0 = unpackbf(Ahs[m][base]);
                Als[m][base] = packbf(x0 - nh0.x, x1 - nh0.y);
                Ahs[m][base + 1] = packbf(x2, x3);
                float2 nh1 = unpackbf(Ahs[m][base + 1]);
                Als[m][base + 1] = packbf(x2 - nh1.x, x3 - nh1.y);
            }
        }
    }

    // ---- output: reconstruct and store ----
#pragma unroll
    for (int n = 0; n < 16; n++) {
        int c0 = 8 * n + 2 * q;
        int m = n >> 1, base = (n & 1) * 2;
        float2 h0 = unpackbf(Ahs[m][base]);
        float2 h1 = unpackbf(Ahs[m][base + 1]);
        float2 l0 = unpackbf(Als[m][base]);
        float2 l1 = unpackbf(Als[m][base + 1]);
        outw[(size_t)c0 * 16384] = h0.x + l0.x;
        outw[(size_t)(c0 + 1) * 16384] = h0.y + l0.y;
        outw[(size_t)c0 * 16384 + 8] = h1.x + l1.x;
        outw[(size_t)(c0 + 1) * 16384 + 8] = h1.y + l1.y;
    }
}

extern "C" void kernel_launch(void* const* d_in, const int* in_sizes, int n_in,
                              void* d_out, int out_size) {
    const float* xn    = (const float*)d_in[0];
    const float* sigma = (const float*)d_in[1];
    const float* Qp    = (const float*)d_in[2];
    const float* tausp = (const float*)d_in[3];
    const float* lamb  = (const float*)d_in[4];
    const float* epso  = (const float*)d_in[5];
    const float* w1    = (const float*)d_in[6];
    const float* b1    = (const float*)d_in[7];
    const float* w2    = (const float*)d_in[8];
    const float* b2    = (const float*)d_in[9];
    const float* w3    = (const float*)d_in[10];
    const float* b3    = (const float*)d_in[11];
    const float* Wf    = (const float*)d_in[12];
    const int* niter   = (const int*)d_in[13];
    float* out = (float*)d_out;

    cudaFuncSetAttribute(mfoe_kernel, cudaFuncAttributeMaxDynamicSharedMemorySize, SMEM_BYTES);
    precomp_kernel<<<1, 64>>>(sigma, Qp, tausp, lamb, epso, w1, b1, w2, b2, w3, b3);
    mfoe_kernel<<<512, THREADS, SMEM_BYTES>>>(xn, Wf, niter, out);
}

// round 13
// speedup vs baseline: 4.1471x; 1.0535x over previous
#include <cuda_runtime.h>
#include <cuda_bf16.h>
#include <cstdint>

#define F_ 48
#define C_ 128
#define GF 192
#define THREADS 128
#define SCALE_C 0.999f

// ---- smem layout (bytes) ----
#define BFS 136   // W row stride in bf16 elems (272B -> conflict-free ldmatrix, trans and non-trans)
#define OFF_W   0                          // W[e][c] bf16, raw
#define OFF_QE  (OFF_W + GF*BFS*2)         // 52224
#define OFF_QM  (OFF_QE + 3072)            // 55296
#define OFF_ISC (OFF_QM + 3072)            // 58368
#define OFF_LSC (OFF_ISC + 192)            // 58560
#define SMEM_BYTES (OFF_LSC + 192)         // 58752

struct Precomp {
    float Qeff[F_][4][4];
    float Qm[F_][4][4];
    float its[F_];
    float invsc[2][F_];
    float lscal[2][F_];
    float eps_e;
    float inv_denom;
};
__device__ Precomp g_pre;

__device__ __forceinline__ uint32_t smem_u32(const void* p) {
    uint32_t a;
    asm("{ .reg .u64 t; cvta.to.shared.u64 t, %1; cvt.u32.u64 %0, t; }" : "=r"(a) : "l"(p));
    return a;
}
// pack: a -> low 16 bits, b -> high
__device__ __forceinline__ uint32_t packbf(float a, float b) {
    uint32_t r;
    asm("cvt.rn.bf16x2.f32 %0, %1, %2;" : "=r"(r) : "f"(b), "f"(a));
    return r;
}
__device__ __forceinline__ float2 unpackbf(uint32_t v) {
    float2 r;
    r.x = __uint_as_float(v << 16);
    r.y = __uint_as_float(v & 0xffff0000u);
    return r;
}
__device__ __forceinline__ void ldsm4(uint32_t* r, uint32_t addr) {
    asm volatile("ldmatrix.sync.aligned.m8n8.x4.shared.b16 {%0,%1,%2,%3}, [%4];"
                 : "=r"(r[0]), "=r"(r[1]), "=r"(r[2]), "=r"(r[3]) : "r"(addr));
}
__device__ __forceinline__ void ldsm4t(uint32_t* r, uint32_t addr) {
    asm volatile("ldmatrix.sync.aligned.m8n8.x4.trans.shared.b16 {%0,%1,%2,%3}, [%4];"
                 : "=r"(r[0]), "=r"(r[1]), "=r"(r[2]), "=r"(r[3]) : "r"(addr));
}
__device__ __forceinline__ void mma16816(float* d, const uint32_t* a, const uint32_t* b) {
    asm volatile(
        "mma.sync.aligned.m16n8k16.row.col.f32.bf16.bf16.f32 "
        "{%0,%1,%2,%3}, {%4,%5,%6,%7}, {%8,%9}, {%0,%1,%2,%3};"
        : "+f"(d[0]), "+f"(d[1]), "+f"(d[2]), "+f"(d[3])
        : "r"(a[0]), "r"(a[1]), "r"(a[2]), "r"(a[3]), "r"(b[0]), "r"(b[1]));
}

__device__ __forceinline__ void proj4(float x0, float x1, float x2, float x3,
                                      float& o0, float& o1, float& o2, float& o3) {
    float a0 = fabsf(x0), a1 = fabsf(x1), a2 = fabsf(x2), a3 = fabsf(x3);
    float ssum = a0 + a1 + a2 + a3;
    float m01 = fmaxf(a0, a1), n01 = fminf(a0, a1);
    float m23 = fmaxf(a2, a3), n23 = fminf(a2, a3);
    float s0 = fmaxf(m01, m23), lo0 = fminf(m01, m23);
    float hi1 = fmaxf(n01, n23), s3 = fminf(n01, n23);
    float s1 = fmaxf(lo0, hi1), s2 = fminf(lo0, hi1);
    float c1 = s0 - 1.f, c2 = c1 + s1, c3 = c2 + s2, c4 = c3 + s3;
    int rho = 1 + (s1 * 2.f > c2) + (s2 * 3.f > c3) + (s3 * 4.f > c4);
    float num = (rho == 1) ? c1 : (rho == 2) ? c2 : (rho == 3) ? c3 : c4;
    float theta = fmaxf(num / (float)rho, 0.f);
    theta = (ssum <= 1.f) ? 0.f : theta;
    o0 = copysignf(fmaxf(a0 - theta, 0.f), x0);
    o1 = copysignf(fmaxf(a1 - theta, 0.f), x1);
    o2 = copysignf(fmaxf(a2 - theta, 0.f), x2);
    o3 = copysignf(fmaxf(a3 - theta, 0.f), x3);
}

// ---------------- precompute kernel (float Jacobi, 12 sweeps) ----------------
__global__ void precomp_kernel(const float* __restrict__ sigma, const float* __restrict__ Qp,
                               const float* __restrict__ tausp, const float* __restrict__ lambp,
                               const float* __restrict__ epsp,
                               const float* __restrict__ w1, const float* __restrict__ b1,
                               const float* __restrict__ w2, const float* __restrict__ b2,
                               const float* __restrict__ w3, const float* __restrict__ b3) {
    __shared__ float h1[2][F_], h2[2][F_];
    int t = threadIdx.x;
    float lamb_e = expf(lambp[0]);
    float eps_e = expf(epsp[0]);
    if (t == 0) {
        g_pre.eps_e = eps_e;
        g_pre.inv_denom = 1.f / (1.f + lamb_e * (1.f + eps_e));
    }
    if (t < F_) {
        float Qm[4][4];
#pragma unroll
        for (int l = 0; l < 4; l++) {
            float rs = 0.f;
#pragma unroll
            for (int g = 0; g < 4; g++) rs += fabsf(Qp[t * 16 + l * 4 + g]);
            float inv = 1.f / fmaxf(rs, 1.f);
#pragma unroll
            for (int g = 0; g < 4; g++) Qm[l][g] = Qp[t * 16 + l * 4 + g] * inv;
        }
        float S[4][4];
        for (int i = 0; i < 4; i++)
            for (int j = 0; j < 4; j++) {
                float acc = 0.f;
                for (int l = 0; l < 4; l++) acc += Qm[l][i] * Qm[l][j];
                S[i][j] = acc;
            }
        const int JP[6] = {0, 0, 0, 1, 1, 2};
        const int JQ[6] = {1, 2, 3, 2, 3, 3};
        for (int sw = 0; sw < 12; sw++)
            for (int rr = 0; rr < 6; rr++) {
                int p = JP[rr], qq = JQ[rr];
                float apq = S[p][qq];
                if (fabsf(apq) < 1e-20f) continue;
                float th = (S[qq][qq] - S[p][p]) / (2.f * apq);
                float tt = (th >= 0.f ? 1.f : -1.f) / (fabsf(th) + sqrtf(1.f + th * th));
                float cc = rsqrtf(1.f + tt * tt), ss = tt * cc;
                for (int k = 0; k < 4; k++) {
                    float skp = S[k][p], skq = S[k][qq];
                    S[k][p] = cc * skp - ss * skq;
                    S[k][qq] = ss * skp + cc * skq;
                }
                for (int k = 0; k < 4; k++) {
                    float spk = S[p][k], sqk = S[qq][k];
                    S[p][k] = cc * spk - ss * sqk;
                    S[qq][k] = ss * spk + cc * sqk;
                }
            }
        float lam = S[0][0];
        for (int i = 1; i < 4; i++) lam = (S[i][i] > lam) ? S[i][i] : lam;
        float inv_lam = 1.f / lam;
#pragma unroll
        for (int l = 0; l < 4; l++)
#pragma unroll
            for (int g = 0; g < 4; g++) {
                g_pre.Qm[t][l][g] = Qm[l][g];
                g_pre.Qeff[t][l][g] = Qm[l][g] * inv_lam;
            }
        g_pre.its[t] = SCALE_C / expf(fmaxf(tausp[t], 0.f));
        for (int bb = 0; bb < 2; bb++)
            h1[bb][t] = fmaxf(fmaf(sigma[bb] * 20.f - 2.f, w1[t], b1[t]), 0.f);
    }
    __syncthreads();
    if (t < F_)
        for (int bb = 0; bb < 2; bb++) {
            float a = b2[t];
            for (int j = 0; j < F_; j++) a += h1[bb][j] * w2[j * F_ + t];
            h2[bb][t] = fmaxf(a, 0.f);
        }
    __syncthreads();
    if (t < F_)
        for (int bb = 0; bb < 2; bb++) {
            float a = b3[t];
            for (int j = 0; j < F_; j++) a += h2[bb][j] * w3[j * F_ + t];
            float sc = fmaxf(fmaf(a, 0.05f, sigma[bb]), 0.f) + 1e-9f;
            g_pre.invsc[bb][t] = 1.f / sc;
            g_pre.lscal[bb][t] = lamb_e * sc;
        }
}

// ---------------- HMMA main kernel: 128 thr, 2 CTAs/SM, streamed Q tables ----------------
__global__ void __launch_bounds__(THREADS, 2)
mfoe_kernel(const float* __restrict__ xn, const float* __restrict__ Wf,
            const int* __restrict__ niter_p, float* __restrict__ out) {
    extern __shared__ char smc[];
    const uint32_t smb = smem_u32(smc);
    const int t = threadIdx.x;
    const int warp = t >> 5, lane = t & 31;
    const int r = lane >> 2, q = lane & 3;
    const int t8 = lane & 7, tb = lane >> 3;

    const int pix0 = blockIdx.x * 64;
    const int b = pix0 >> 14;
    const int sp0 = pix0 & 16383;
    const float* xnw = xn + (size_t)b * (C_ * 16384) + sp0 + warp * 16 + r;
    float* outw = out + (size_t)b * (C_ * 16384) + sp0 + warp * 16 + r;

    // ---- fill shared W tile (raw bf16) + Q tables + per-f scalars ----
    {
        __nv_bfloat16* wt = (__nv_bfloat16*)(smc + OFF_W);
        for (int i = t; i < GF * C_; i += THREADS) {
            int e = i >> 7, c = i & 127;
            wt[e * BFS + c] = __float2bfloat16(Wf[i]);
        }
        float* qes = (float*)(smc + OFF_QE);
        float* qms = (float*)(smc + OFF_QM);
        for (int i = t; i < 768; i += THREADS) {
            qes[i] = ((const float*)g_pre.Qeff)[i] * g_pre.its[i >> 4];
            qms[i] = ((const float*)g_pre.Qm)[i] * SCALE_C;
        }
        if (t < F_) {
            ((float*)(smc + OFF_ISC))[t] = g_pre.invsc[b][t];
            ((float*)(smc + OFF_LSC))[t] = g_pre.lscal[b][t];
        }
    }
    __syncthreads();

    const float eps_e = g_pre.eps_e;
    const float inv_denom = g_pre.inv_denom;
    const int niter = *niter_p;
    const float* qes = (const float*)(smc + OFF_QE);
    const float* qms = (const float*)(smc + OFF_QM);
    const float* ISC = (const float*)(smc + OFF_ISC);
    const float* LSC = (const float*)(smc + OFF_LSC);

    // ---- x state as packed bf16 hi/lo A-fragments ----
    uint32_t Ahs[8][4], Als[8][4];
#pragma unroll
    for (int n = 0; n < 16; n++) {
        int c0 = 8 * n + 2 * q;
        float x0 = xnw[(size_t)c0 * 16384];
        float x1 = xnw[(size_t)(c0 + 1) * 16384];
        float x2 = xnw[(size_t)c0 * 16384 + 8];
        float x3 = xnw[(size_t)(c0 + 1) * 16384 + 8];
        int m = n >> 1, base = (n & 1) * 2;
        Ahs[m][base] = packbf(x0, x1);
        float2 h0 = unpackbf(Ahs[m][base]);
        Als[m][base] = packbf(x0 - h0.x, x1 - h0.y);
        Ahs[m][base + 1] = packbf(x2, x3);
        float2 h1 = unpackbf(Ahs[m][base + 1]);
        Als[m][base + 1] = packbf(x2 - h1.x, x3 - h1.y);
    }

    for (int it = 0; it < niter; ++it) {
        uint32_t vh[24][2];   // v tiles, packed bf16

        // ===== forward (2-term: exact x, bf16 W) + activation =====
#pragma unroll
        for (int r6 = 0; r6 < 6; r6++) {
            float Df[4][4];
#pragma unroll
            for (int g = 0; g < 4; g++) { Df[g][0] = 0.f; Df[g][1] = 0.f; Df[g][2] = 0.f; Df[g][3] = 0.f; }
#pragma unroll
            for (int jp = 0; jp < 4; jp++) {
                uint32_t rowoff = smb + OFF_W + (uint32_t)(t8 * BFS + 32 * jp + 8 * tb) * 2;
#pragma unroll
                for (int g = 0; g < 4; g++) {
                    int n = r6 + 6 * g;
                    uint32_t bh[4];
                    ldsm4(bh, rowoff + (uint32_t)(8 * n * BFS) * 2);
                    mma16816(Df[g], Ahs[2 * jp], bh);
                    mma16816(Df[g], Als[2 * jp], bh);
                    mma16816(Df[g], Ahs[2 * jp + 1], bh + 2);
                    mma16816(Df[g], Als[2 * jp + 1], bh + 2);
                }
            }

            // activation on the quad -> vh[e-tile = r6 + 6g]; Q tables streamed (<=1 float4 live)
            {
                float vt[2][2][4];   // [h][fcol][g]
#pragma unroll
                for (int fcol = 0; fcol < 2; fcol++) {
                    int f = 8 * r6 + 2 * q + fcol;
                    float isc = ISC[f];
                    float ls  = LSC[f];
#pragma unroll
                    for (int h = 0; h < 2; h++) {
                        int di = 2 * h + fcol;
                        float xv0 = Df[0][di] * isc, xv1 = Df[1][di] * isc;
                        float xv2 = Df[2][di] * isc, xv3 = Df[3][di] * isc;

                        float gc0, gc1, gc2, gc3;
                        proj4(xv0, xv1, xv2, xv3, gc0, gc1, gc2, gc3);
                        gc0 = fmaf(eps_e, xv0, gc0);
                        gc1 = fmaf(eps_e, xv1, gc1);
                        gc2 = fmaf(eps_e, xv2, gc2);
                        gc3 = fmaf(eps_e, xv3, gc3);

                        float y[4];
#pragma unroll
                        for (int l = 0; l < 4; l++) {
                            float4 qe = *(const float4*)(qes + f * 16 + 4 * l);
                            y[l] = qe.x * xv0 + qe.y * xv1 + qe.z * xv2 + qe.w * xv3;
                        }

                        float gy[4];
                        proj4(y[0], y[1], y[2], y[3], gy[0], gy[1], gy[2], gy[3]);
#pragma unroll
                        for (int l = 0; l < 4; l++) gy[l] = fmaf(eps_e, y[l], gy[l]);

                        float v0 = gc0, v1 = gc1, v2 = gc2, v3 = gc3;
#pragma unroll
                        for (int l = 0; l < 4; l++) {
                            float4 qm = *(const float4*)(qms + f * 16 + 4 * l);
                            v0 -= qm.x * gy[l];
                            v1 -= qm.y * gy[l];
                            v2 -= qm.z * gy[l];
                            v3 -= qm.w * gy[l];
                        }
                        vt[h][fcol][0] = ls * v0;
                        vt[h][fcol][1] = ls * v1;
                        vt[h][fcol][2] = ls * v2;
                        vt[h][fcol][3] = ls * v3;
                    }
                }
#pragma unroll
                for (int g = 0; g < 4; g++) {
                    vh[r6 + 6 * g][0] = packbf(vt[0][0][g], vt[0][1][g]);
                    vh[r6 + 6 * g][1] = packbf(vt[1][0][g], vt[1][1][g]);
                }
            }
        }

        // ===== backward (1-term, trans-ldsm from the SAME W tile) + x update =====
#pragma unroll
        for (int p = 0; p < 8; p++) {
            float acc0[4] = {0.f, 0.f, 0.f, 0.f};
            float acc1[4] = {0.f, 0.f, 0.f, 0.f};
            uint32_t coloff = (uint32_t)(16 * p + 8 * (tb >> 1)) * 2;
            uint32_t rowb = (uint32_t)(t8 + 8 * (tb & 1));
#pragma unroll
            for (int jp = 0; jp < 12; jp++) {
                uint32_t bt[4];
                ldsm4t(bt, smb + OFF_W + (uint32_t)((16 * jp + rowb) * BFS) * 2 + coloff);
                uint32_t A[4] = {vh[2 * jp][0], vh[2 * jp][1], vh[2 * jp + 1][0], vh[2 * jp + 1][1]};
                mma16816(acc0, A, bt);
                mma16816(acc1, A, bt + 2);
            }
#pragma unroll
            for (int s = 0; s < 2; s++) {
                const float* ac = s ? acc1 : acc0;
                int n = 2 * p + s;
                int c0 = 8 * n + 2 * q;
                float n0 = xnw[(size_t)c0 * 16384];
                float n1 = xnw[(size_t)(c0 + 1) * 16384];
                float n2 = xnw[(size_t)c0 * 16384 + 8];
                float n3 = xnw[(size_t)(c0 + 1) * 16384 + 8];
                int m = p, base = s * 2;
                float2 h0 = unpackbf(Ahs[m][base]);
                float2 h1 = unpackbf(Ahs[m][base + 1]);
                float2 l0 = unpackbf(Als[m][base]);
                float2 l1 = unpackbf(Als[m][base + 1]);
                float x0 = h0.x + l0.x, x1 = h0.y + l0.y;
                float x2 = h1.x + l1.x, x3 = h1.y + l1.y;
                x0 -= (x0 - n0 + ac[0]) * inv_denom;
                x1 -= (x1 - n1 + ac[1]) * inv_denom;
                x2 -= (x2 - n2 + ac[2]) * inv_denom;
                x3 -= (x3 - n3 + ac[3]) * inv_denom;
                Ahs[m][base] = packbf(x0, x1);
                float2 nh0 = unpackbf(Ahs[m][base]);
                Als[m][base] = packbf(x0 - nh0.x, x1 - nh0.y);
                Ahs[m][base + 1] = packbf(x2, x3);
                float2 nh1 = unpackbf(Ahs[m][base + 1]);
                Als[m][base + 1] = packbf(x2 - nh1.x, x3 - nh1.y);
            }
        }
    }

    // ---- output: reconstruct and store ----
#pragma unroll
    for (int n = 0; n < 16; n++) {
        int c0 = 8 * n + 2 * q;
        int m = n >> 1, base = (n & 1) * 2;
        float2 h0 = unpackbf(Ahs[m][base]);
        float2 h1 = unpackbf(Ahs[m][base + 1]);
        float2 l0 = unpackbf(Als[m][base]);
        float2 l1 = unpackbf(Als[m][base + 1]);
        outw[(size_t)c0 * 16384] = h0.x + l0.x;
        outw[(size_t)(c0 + 1) * 16384] = h0.y + l0.y;
        outw[(size_t)c0 * 16384 + 8] = h1.x + l1.x;
        outw[(size_t)(c0 + 1) * 16384 + 8] = h1.y + l1.y;
    }
}

extern "C" void kernel_launch(void* const* d_in, const int* in_sizes, int n_in,
                              void* d_out, int out_size) {
    const float* xn    = (const float*)d_in[0];
    const float* sigma = (const float*)d_in[1];
    const float* Qp    = (const float*)d_in[2];
    const float* tausp = (const float*)d_in[3];
    const float* lamb  = (const float*)d_in[4];
    const float* epso  = (const float*)d_in[5];
    const float* w1    = (const float*)d_in[6];
    const float* b1    = (const float*)d_in[7];
    const float* w2    = (const float*)d_in[8];
    const float* b2    = (const float*)d_in[9];
    const float* w3    = (const float*)d_in[10];
    const float* b3    = (const float*)d_in[11];
    const float* Wf    = (const float*)d_in[12];
    const int* niter   = (const int*)d_in[13];
    float* out = (float*)d_out;

    cudaFuncSetAttribute(mfoe_kernel, cudaFuncAttributeMaxDynamicSharedMemorySize, SMEM_BYTES);
    precomp_kernel<<<1, 64>>>(sigma, Qp, tausp, lamb, epso, w1, b1, w2, b2, w3, b3);
    mfoe_kernel<<<512, THREADS, SMEM_BYTES>>>(xn, Wf, niter, out);
}